// round 9
// baseline (speedup 1.0000x reference)
#include <cuda_runtime.h>
#include <cuda_bf16.h>
#include <cstdint>

#define BB 4
#define SS 2048
#define EE 1024
#define HH 16
#define DD 64
#define BSROWS (BB * SS)   // 8192

// Scratch (device globals; allocation-free per harness rules).
__device__ float g_q[BSROWS * EE];
__device__ float g_k[BSROWS * EE];
__device__ float g_v[BSROWS * EE];
__device__ float g_attn[BSROWS * EE];
__device__ float g_xc[BSROWS * EE];
__device__ float g_wq[EE * EE];
__device__ float g_wk[EE * EE];
__device__ float g_wv[EE * EE];
__device__ float g_wo[EE * EE];

// ---------------------------------------------------------------------------
// helpers
// ---------------------------------------------------------------------------
__device__ __forceinline__ uint32_t smem_u32(const void* p) {
    uint32_t a;
    asm("{ .reg .u64 t; cvta.to.shared.u64 t, %1; cvt.u32.u64 %0, t; }" : "=r"(a) : "l"(p));
    return a;
}
__device__ __forceinline__ uint32_t f2tf32(float f) {
    uint32_t r;
    asm("cvt.rna.tf32.f32 %0, %1;" : "=r"(r) : "f"(f));
    return r;
}
__device__ __forceinline__ float tfr(float f) {
    return __uint_as_float(f2tf32(f));
}
__device__ __forceinline__ void cp_async16(uint32_t dst, const void* src) {
    asm volatile("cp.async.ca.shared.global [%0], [%1], 16;" :: "r"(dst), "l"(src));
}
#define CP_COMMIT() asm volatile("cp.async.commit_group;" ::: "memory")
#define CP_WAIT(n)  asm volatile("cp.async.wait_group %0;" :: "n"(n) : "memory")

__device__ __forceinline__ void mma_tf32(float* c, const uint32_t* a, const uint32_t* b) {
    asm volatile(
        "mma.sync.aligned.m16n8k8.row.col.f32.tf32.tf32.f32 "
        "{%0,%1,%2,%3}, {%4,%5,%6,%7}, {%8,%9}, {%0,%1,%2,%3};"
        : "+f"(c[0]), "+f"(c[1]), "+f"(c[2]), "+f"(c[3])
        : "r"(a[0]), "r"(a[1]), "r"(a[2]), "r"(a[3]), "r"(b[0]), "r"(b[1]));
}

// k-group permutation (verified R7/R8): phys = [l0,l4,l1,l5,l2,l6,l3,l7]
__device__ __forceinline__ int kperm(int c) { return 2 * (c & 3) + ((c & 4) >> 2); }

// ---------------------------------------------------------------------------
// prep: tf32-round + permute 8-float groups, GMEM -> GMEM
// ---------------------------------------------------------------------------
__global__ void prep_perm(const float* __restrict__ src, float* __restrict__ dst, int ngroups)
{
    int i = blockIdx.x * blockDim.x + threadIdx.x;
    if (i >= ngroups) return;
    const float4* s = (const float4*)(src + 8L * i);
    float4 a = s[0], b = s[1];
    float4 o0 = make_float4(tfr(a.x), tfr(b.x), tfr(a.y), tfr(b.y));
    float4 o1 = make_float4(tfr(a.z), tfr(b.z), tfr(a.w), tfr(b.w));
    float4* d = (float4*)(dst + 8L * i);
    d[0] = o0; d[1] = o1;
}

// ---------------------------------------------------------------------------
// tf32 mma.sync GEMM, pre-converted inputs, ONE __syncthreads per k-chunk.
// CTA 128x128, BK=32, 8 warps (2x4), warp tile 64x32, 2-stage cp.async.
// mode: 0 = fp32 out (+bias), 1 = tf32 permuted out, 2 = tf32 rounded out.
// ---------------------------------------------------------------------------
#define BK 32
#define SSTR 36
#define TILE_F (128 * SSTR)
#define NCHUNK (EE / BK)

__global__ void __launch_bounds__(256)
gemm_tf32(const float* __restrict__ A, const float* __restrict__ W,
          const float* __restrict__ bias, float* __restrict__ C, int mode)
{
    extern __shared__ float sm[];
    const uint32_t smb = smem_u32(sm);

    const int t    = threadIdx.x;
    const int brow = blockIdx.y * 128;
    const int bcol = blockIdx.x * 128;

    const int lane = t & 31;
    const int w    = t >> 5;
    const int wm   = (w & 1) * 64;
    const int wn   = (w >> 1) * 32;
    const int g    = lane >> 2;
    const int tg   = lane & 3;

    const int sr = t >> 1;
    const int sc = (t & 1) * 16;
    const float* Ag = A + (long)(brow + sr) * EE + sc;
    const float* Wg = W + (long)(bcol + sr) * EE + sc;
    const uint32_t sdA = smb + (sr * SSTR + sc) * 4;
    const uint32_t sdW = sdA + TILE_F * 4;

    float acc[4][4][4];
#pragma unroll
    for (int i = 0; i < 4; i++)
#pragma unroll
        for (int j = 0; j < 4; j++)
#pragma unroll
            for (int r = 0; r < 4; r++) acc[i][j][r] = 0.f;

    // prologue: stage chunk 0 -> buffer 0
#pragma unroll
    for (int j = 0; j < 4; j++) {
        cp_async16(sdA + j * 16, Ag + j * 4);
        cp_async16(sdW + j * 16, Wg + j * 4);
    }
    CP_COMMIT();

    for (int kc = 0; kc < NCHUNK; kc++) {
        const int cur = kc & 1, nxt = cur ^ 1;

        CP_WAIT(0);          // chunk kc staged (only group in flight)
        __syncthreads();     // data visible AND prev compute done -> nxt reusable

        if (kc + 1 < NCHUNK) {
            const int k0 = (kc + 1) * BK;
            const uint32_t bofs = nxt * 2 * TILE_F * 4;
#pragma unroll
            for (int j = 0; j < 4; j++) {
                cp_async16(sdA + bofs + j * 16, Ag + k0 + j * 4);
                cp_async16(sdW + bofs + j * 16, Wg + k0 + j * 4);
            }
            CP_COMMIT();
        }

        const float* As = sm + cur * 2 * TILE_F;
        const float* Ws = As + TILE_F;
        const int pa = (wm + g) * SSTR + 2 * tg;
        const int pb = (wn + g) * SSTR + 2 * tg;

#pragma unroll
        for (int kk = 0; kk < 4; kk++) {
            uint32_t af[4][4], bf[4][2];
#pragma unroll
            for (int mt = 0; mt < 4; mt++) {
                const int ib = pa + mt * 16 * SSTR + kk * 8;
                float2 x0 = *(const float2*)&As[ib];
                float2 x1 = *(const float2*)&As[ib + 8 * SSTR];
                af[mt][0] = __float_as_uint(x0.x);
                af[mt][1] = __float_as_uint(x1.x);
                af[mt][2] = __float_as_uint(x0.y);
                af[mt][3] = __float_as_uint(x1.y);
            }
#pragma unroll
            for (int nt = 0; nt < 4; nt++) {
                const int ib = pb + nt * 8 * SSTR + kk * 8;
                float2 y = *(const float2*)&Ws[ib];
                bf[nt][0] = __float_as_uint(y.x);
                bf[nt][1] = __float_as_uint(y.y);
            }
#pragma unroll
            for (int mt = 0; mt < 4; mt++)
#pragma unroll
                for (int nt = 0; nt < 4; nt++)
                    mma_tf32(acc[mt][nt], af[mt], bf[nt]);
        }
    }

    if (mode == 0) {
#pragma unroll
        for (int mt = 0; mt < 4; mt++)
#pragma unroll
            for (int nt = 0; nt < 4; nt++) {
                const int row = brow + wm + mt * 16 + g;
                const int col = bcol + wn + nt * 8 + 2 * tg;
                float b0 = bias ? bias[col] : 0.f;
                float b1 = bias ? bias[col + 1] : 0.f;
                *(float2*)(C + (long)row * EE + col) =
                    make_float2(acc[mt][nt][0] + b0, acc[mt][nt][1] + b1);
                *(float2*)(C + (long)(row + 8) * EE + col) =
                    make_float2(acc[mt][nt][2] + b0, acc[mt][nt][3] + b1);
            }
    } else if (mode == 1) {      // tf32 rounded + permuted (Q, K)
        const int p0 = kperm(2 * tg), p1 = kperm(2 * tg + 1);
#pragma unroll
        for (int mt = 0; mt < 4; mt++)
#pragma unroll
            for (int nt = 0; nt < 4; nt++) {
                const int row = brow + wm + mt * 16 + g;
                const int cb  = bcol + wn + nt * 8;
                C[(long)row * EE + cb + p0]       = tfr(acc[mt][nt][0]);
                C[(long)row * EE + cb + p1]       = tfr(acc[mt][nt][1]);
                C[(long)(row + 8) * EE + cb + p0] = tfr(acc[mt][nt][2]);
                C[(long)(row + 8) * EE + cb + p1] = tfr(acc[mt][nt][3]);
            }
    } else {                     // tf32 rounded, unpermuted (V)
#pragma unroll
        for (int mt = 0; mt < 4; mt++)
#pragma unroll
            for (int nt = 0; nt < 4; nt++) {
                const int row = brow + wm + mt * 16 + g;
                const int col = bcol + wn + nt * 8 + 2 * tg;
                *(float2*)(C + (long)row * EE + col) =
                    make_float2(tfr(acc[mt][nt][0]), tfr(acc[mt][nt][1]));
                *(float2*)(C + (long)(row + 8) * EE + col) =
                    make_float2(tfr(acc[mt][nt][2]), tfr(acc[mt][nt][3]));
            }
    }
}

// ---------------------------------------------------------------------------
// Tensor-core flash attention, pre-converted Q/K (permuted tf32) + V (tf32).
// 2-stage KV ring, ONE __syncthreads per KV tile.
// ---------------------------------------------------------------------------
#define KST 72
#define VST 72
#define PST 68
#define KVBUF (64 * KST + 64 * VST)              // 9216 floats per buffer
#define NEG_BIG (-1e30f)
#define FLASH_SMEMF (2 * KVBUF + 8 * 16 * PST)   // 27136 floats = 108544 B

__global__ void __launch_bounds__(256, 2)
flash_tc(const float* __restrict__ Qg, const float* __restrict__ Kg,
         const float* __restrict__ Vg, float* __restrict__ Og)
{
    extern __shared__ float smem[];
    float* Qs = smem;                        // [128][KST] staging (over KV bufs)
    float* Ps = smem + 2 * KVBUF;

    const uint32_t smb = smem_u32(smem);
    const int tid = threadIdx.x;
    const int w = tid >> 5, lane = tid & 31;
    const int g = lane >> 2, tg = lane & 3;
    const int qt = blockIdx.x;
    const int b = blockIdx.y / HH, h = blockIdx.y % HH;
    const int wm = w * 16;
    const int qlo = qt * 128 + wm;

    const float* Qb = Qg + (long)b * SS * EE + h * DD;
    const float* Kb = Kg + (long)b * SS * EE + h * DD;
    const float* Vb = Vg + (long)b * SS * EE + h * DD;
    float*       Ob = Og + (long)b * SS * EE + h * DD;

    // ---- stage Q (rounded+permuted), extract scaled fragments ----
    {
        const int r = tid >> 1, c = (tid & 1) * 32;
        const float* src = Qb + (long)(qt * 128 + r) * EE + c;
        const uint32_t dst = smb + (r * KST + c) * 4;
#pragma unroll
        for (int j = 0; j < 8; j++) cp_async16(dst + j * 16, src + j * 4);
        CP_COMMIT(); CP_WAIT(0);
    }
    __syncthreads();

    uint32_t qf[8][4];
    const float sc = 0.03125f;   // 1/sqrt(1024); x2^-5 exact in tf32
#pragma unroll
    for (int ks = 0; ks < 8; ks++) {
        float2 q0 = *(const float2*)&Qs[(wm + g)     * KST + 8 * ks + 2 * tg];
        float2 q1 = *(const float2*)&Qs[(wm + g + 8) * KST + 8 * ks + 2 * tg];
        qf[ks][0] = __float_as_uint(q0.x * sc);
        qf[ks][1] = __float_as_uint(q1.x * sc);
        qf[ks][2] = __float_as_uint(q0.y * sc);
        qf[ks][3] = __float_as_uint(q1.y * sc);
    }
    __syncthreads();

    float of[8][4];
#pragma unroll
    for (int i = 0; i < 8; i++)
#pragma unroll
        for (int j = 0; j < 4; j++) of[i][j] = 0.f;
    float m0 = NEG_BIG, m1 = NEG_BIG, l0 = 0.f, l1 = 0.f;
    float* Pw = Ps + w * 16 * PST;

    const int lr = tid >> 2, lc = (tid & 3) * 16;
    const int ntiles = 2 * qt + 2;

    // prologue: tile 0 -> buf 0
    {
        const float* ksrc = Kb + (long)lr * EE + lc;
        const float* vsrc = Vb + (long)lr * EE + lc;
        const uint32_t kdst = smb + (lr * KST + lc) * 4;
        const uint32_t vdst = smb + (64 * KST + lr * VST + lc) * 4;
#pragma unroll
        for (int j = 0; j < 4; j++) cp_async16(kdst + j * 16, ksrc + j * 4);
#pragma unroll
        for (int j = 0; j < 4; j++) cp_async16(vdst + j * 16, vsrc + j * 4);
        CP_COMMIT();
    }

    for (int kt = 0; kt < ntiles; kt++) {
        const int cur = kt & 1, nxt = cur ^ 1;

        CP_WAIT(0);          // tile kt staged
        __syncthreads();     // visible to all; prev compute done -> nxt reusable

        if (kt + 1 < ntiles) {
            const long roff = (long)((kt + 1) * 64 + lr) * EE + lc;
            const uint32_t kdst = smb + (nxt * KVBUF + lr * KST + lc) * 4;
            const uint32_t vdst = smb + (nxt * KVBUF + 64 * KST + lr * VST + lc) * 4;
#pragma unroll
            for (int j = 0; j < 4; j++) cp_async16(kdst + j * 16, Kb + roff + j * 4);
#pragma unroll
            for (int j = 0; j < 4; j++) cp_async16(vdst + j * 16, Vb + roff + j * 4);
            CP_COMMIT();
        }

        const float* Ks = smem + cur * KVBUF;
        const float* Vs = Ks + 64 * KST;

        if (kt * 64 <= qlo + 15) {
            // ---- S = Q K^T ----
            float s[8][4];
#pragma unroll
            for (int nt = 0; nt < 8; nt++) {
                float c4[4] = {0.f, 0.f, 0.f, 0.f};
#pragma unroll
                for (int ks = 0; ks < 8; ks++) {
                    float2 kk2 = *(const float2*)&Ks[(nt * 8 + g) * KST + ks * 8 + 2 * tg];
                    uint32_t bb[2] = {__float_as_uint(kk2.x), __float_as_uint(kk2.y)};
                    mma_tf32(c4, qf[ks], bb);
                }
                s[nt][0] = c4[0]; s[nt][1] = c4[1]; s[nt][2] = c4[2]; s[nt][3] = c4[3];
            }

            // ---- causal mask ----
            if (kt * 64 + 63 > qlo) {
                const int r0g = qlo + g, r1g = qlo + g + 8;
#pragma unroll
                for (int nt = 0; nt < 8; nt++) {
                    const int col = kt * 64 + nt * 8 + 2 * tg;
                    if (col     > r0g) s[nt][0] = NEG_BIG;
                    if (col + 1 > r0g) s[nt][1] = NEG_BIG;
                    if (col     > r1g) s[nt][2] = NEG_BIG;
                    if (col + 1 > r1g) s[nt][3] = NEG_BIG;
                }
            }

            // ---- online softmax ----
            float a0 = NEG_BIG, a1 = NEG_BIG;
#pragma unroll
            for (int nt = 0; nt < 8; nt++) {
                a0 = fmaxf(a0, fmaxf(s[nt][0], s[nt][1]));
                a1 = fmaxf(a1, fmaxf(s[nt][2], s[nt][3]));
            }
            a0 = fmaxf(a0, __shfl_xor_sync(0xffffffffu, a0, 1));
            a0 = fmaxf(a0, __shfl_xor_sync(0xffffffffu, a0, 2));
            a1 = fmaxf(a1, __shfl_xor_sync(0xffffffffu, a1, 1));
            a1 = fmaxf(a1, __shfl_xor_sync(0xffffffffu, a1, 2));

            const float mn0 = fmaxf(m0, a0), mn1 = fmaxf(m1, a1);
            const float cf0 = __expf(m0 - mn0), cf1 = __expf(m1 - mn1);
            m0 = mn0; m1 = mn1;

            float sum0 = 0.f, sum1 = 0.f;
#pragma unroll
            for (int nt = 0; nt < 8; nt++) {
                float p0 = __expf(s[nt][0] - m0);
                float p1 = __expf(s[nt][1] - m0);
                float p2 = __expf(s[nt][2] - m1);
                float p3 = __expf(s[nt][3] - m1);
                sum0 += p0 + p1; sum1 += p2 + p3;
                *(float2*)&Pw[g       * PST + nt * 8 + 2 * tg] = make_float2(p0, p1);
                *(float2*)&Pw[(g + 8) * PST + nt * 8 + 2 * tg] = make_float2(p2, p3);
            }
            sum0 += __shfl_xor_sync(0xffffffffu, sum0, 1);
            sum0 += __shfl_xor_sync(0xffffffffu, sum0, 2);
            sum1 += __shfl_xor_sync(0xffffffffu, sum1, 1);
            sum1 += __shfl_xor_sync(0xffffffffu, sum1, 2);
            l0 = l0 * cf0 + sum0;
            l1 = l1 * cf1 + sum1;
#pragma unroll
            for (int nt = 0; nt < 8; nt++) {
                of[nt][0] *= cf0; of[nt][1] *= cf0;
                of[nt][2] *= cf1; of[nt][3] *= cf1;
            }
            __syncwarp();

            // ---- O += P V ----
#pragma unroll
            for (int ks = 0; ks < 8; ks++) {
                uint32_t af[4];
                af[0] = f2tf32(Pw[g       * PST + tg     + 8 * ks]);
                af[1] = f2tf32(Pw[(g + 8) * PST + tg     + 8 * ks]);
                af[2] = f2tf32(Pw[g       * PST + tg + 4 + 8 * ks]);
                af[3] = f2tf32(Pw[(g + 8) * PST + tg + 4 + 8 * ks]);
#pragma unroll
                for (int dn = 0; dn < 8; dn++) {
                    uint32_t bb[2];
                    bb[0] = __float_as_uint(Vs[(tg     + 8 * ks) * VST + dn * 8 + g]);
                    bb[1] = __float_as_uint(Vs[(tg + 4 + 8 * ks) * VST + dn * 8 + g]);
                    mma_tf32(of[dn], af, bb);
                }
            }
        }
    }

    // ---- epilogue: normalize, round, permute-store (feeds Wo GEMM) ----
    const float i0 = 1.f / l0, i1 = 1.f / l1;
    const int r0g = qt * 128 + wm + g, r1g = r0g + 8;
    const int p0 = kperm(2 * tg), p1 = kperm(2 * tg + 1);
#pragma unroll
    for (int dn = 0; dn < 8; dn++) {
        const int cb = dn * 8;
        Ob[(long)r0g * EE + cb + p0] = tfr(of[dn][0] * i0);
        Ob[(long)r0g * EE + cb + p1] = tfr(of[dn][1] * i0);
        Ob[(long)r1g * EE + cb + p0] = tfr(of[dn][2] * i1);
        Ob[(long)r1g * EE + cb + p1] = tfr(of[dn][3] * i1);
    }
}

// ---------------------------------------------------------------------------
extern "C" void kernel_launch(void* const* d_in, const int* in_sizes, int n_in,
                              void* d_out, int out_size)
{
    const float* x  = (const float*)d_in[0];
    const float* Wq = (const float*)d_in[1];
    const float* Wk = (const float*)d_in[2];
    const float* Wv = (const float*)d_in[3];
    const float* Wo = (const float*)d_in[4];
    const float* bo = (const float*)d_in[5];
    float* out = (float*)d_out;

    float *q, *k, *v, *a, *xc, *wq, *wk, *wv, *wo;
    cudaGetSymbolAddress((void**)&q,  g_q);
    cudaGetSymbolAddress((void**)&k,  g_k);
    cudaGetSymbolAddress((void**)&v,  g_v);
    cudaGetSymbolAddress((void**)&a,  g_attn);
    cudaGetSymbolAddress((void**)&xc, g_xc);
    cudaGetSymbolAddress((void**)&wq, g_wq);
    cudaGetSymbolAddress((void**)&wk, g_wk);
    cudaGetSymbolAddress((void**)&wv, g_wv);
    cudaGetSymbolAddress((void**)&wo, g_wo);

    const int xg = BSROWS * EE / 8, wg = EE * EE / 8;
    prep_perm<<<(xg + 255) / 256, 256>>>(x,  xc, xg);
    prep_perm<<<(wg + 255) / 256, 256>>>(Wq, wq, wg);
    prep_perm<<<(wg + 255) / 256, 256>>>(Wk, wk, wg);
    prep_perm<<<(wg + 255) / 256, 256>>>(Wv, wv, wg);
    prep_perm<<<(wg + 255) / 256, 256>>>(Wo, wo, wg);

    const int gemm_smem = 4 * TILE_F * sizeof(float);   // 73728 B
    cudaFuncSetAttribute(gemm_tf32,
                         cudaFuncAttributeMaxDynamicSharedMemorySize, gemm_smem);

    dim3 gg(EE / 128, BSROWS / 128);   // (8, 64)
    gemm_tf32<<<gg, 256, gemm_smem>>>(xc, wq, nullptr, q, 1);
    gemm_tf32<<<gg, 256, gemm_smem>>>(xc, wk, nullptr, k, 1);
    gemm_tf32<<<gg, 256, gemm_smem>>>(xc, wv, nullptr, v, 2);

    const int flash_smem = FLASH_SMEMF * sizeof(float);  // 108544 B
    cudaFuncSetAttribute(flash_tc,
                         cudaFuncAttributeMaxDynamicSharedMemorySize, flash_smem);
    flash_tc<<<dim3(SS / 128, BB * HH), 256, flash_smem>>>(q, k, v, a);

    gemm_tf32<<<gg, 256, gemm_smem>>>(a, wo, bo, out, 0);
}

// round 10
// speedup vs baseline: 1.0741x; 1.0741x over previous
#include <cuda_runtime.h>
#include <cuda_bf16.h>
#include <cstdint>

#define BB 4
#define SS 2048
#define EE 1024
#define HH 16
#define DD 64
#define BSROWS (BB * SS)   // 8192

// Scratch (device globals; allocation-free per harness rules).
__device__ float g_q[BSROWS * EE];
__device__ float g_k[BSROWS * EE];
__device__ float g_v[BSROWS * EE];
__device__ float g_attn[BSROWS * EE];

// ---------------------------------------------------------------------------
// helpers
// ---------------------------------------------------------------------------
__device__ __forceinline__ uint32_t smem_u32(const void* p) {
    uint32_t a;
    asm("{ .reg .u64 t; cvta.to.shared.u64 t, %1; cvt.u32.u64 %0, t; }" : "=r"(a) : "l"(p));
    return a;
}
__device__ __forceinline__ uint32_t f2tf32(float f) {
    uint32_t r;
    asm("cvt.rna.tf32.f32 %0, %1;" : "=r"(r) : "f"(f));
    return r;
}
__device__ __forceinline__ void cp_async16(uint32_t dst, const void* src) {
    asm volatile("cp.async.ca.shared.global [%0], [%1], 16;" :: "r"(dst), "l"(src));
}
#define CP_COMMIT() asm volatile("cp.async.commit_group;" ::: "memory")
#define CP_WAIT(n)  asm volatile("cp.async.wait_group %0;" :: "n"(n) : "memory")

__device__ __forceinline__ void mma_tf32(float* c, const uint32_t* a, const uint32_t* b) {
    asm volatile(
        "mma.sync.aligned.m16n8k8.row.col.f32.tf32.tf32.f32 "
        "{%0,%1,%2,%3}, {%4,%5,%6,%7}, {%8,%9}, {%0,%1,%2,%3};"
        : "+f"(c[0]), "+f"(c[1]), "+f"(c[2]), "+f"(c[3])
        : "r"(a[0]), "r"(a[1]), "r"(a[2]), "r"(a[3]), "r"(b[0]), "r"(b[1]));
}

// ---------------------------------------------------------------------------
// GEMM body (R6-identical numerics): C[128,128] tile of A[M,K] * W[N,K]^T.
// CTA 128x128, BK=32, 8 warps (2x4), warp tile 64x32, 2-stage cp.async.
// ---------------------------------------------------------------------------
#define BK 32
#define SSTR 36
#define TILE_F (128 * SSTR)
#define NCHUNK (EE / BK)

__device__ __forceinline__ void gemm_body(
    const float* __restrict__ A, const float* __restrict__ W,
    const float* __restrict__ bias, float* __restrict__ C,
    int brow, int bcol, float* sm, uint32_t smb)
{
    const int t    = threadIdx.x;
    const int lane = t & 31;
    const int w    = t >> 5;
    const int wm   = (w & 1) * 64;
    const int wn   = (w >> 1) * 32;
    const int g    = lane >> 2;
    const int tg   = lane & 3;

    const int sr = t >> 1;
    const int sc = (t & 1) * 16;
    const float* Ag = A + (long)(brow + sr) * EE + sc;
    const float* Wg = W + (long)(bcol + sr) * EE + sc;
    const uint32_t sdA = smb + (sr * SSTR + sc) * 4;
    const uint32_t sdW = sdA + TILE_F * 4;

    float acc[4][4][4];
#pragma unroll
    for (int i = 0; i < 4; i++)
#pragma unroll
        for (int j = 0; j < 4; j++)
#pragma unroll
            for (int r = 0; r < 4; r++) acc[i][j][r] = 0.f;

#pragma unroll
    for (int j = 0; j < 4; j++) {
        cp_async16(sdA + j * 16, Ag + j * 4);
        cp_async16(sdW + j * 16, Wg + j * 4);
    }
    CP_COMMIT();

    for (int kc = 0; kc < NCHUNK; kc++) {
        const int cur = kc & 1, nxt = cur ^ 1;

        if (kc + 1 < NCHUNK) {
            const int k0 = (kc + 1) * BK;
            const uint32_t bofs = nxt * 2 * TILE_F * 4;
#pragma unroll
            for (int j = 0; j < 4; j++) {
                cp_async16(sdA + bofs + j * 16, Ag + k0 + j * 4);
                cp_async16(sdW + bofs + j * 16, Wg + k0 + j * 4);
            }
            CP_COMMIT();
            CP_WAIT(1);
        } else {
            CP_WAIT(0);
        }
        __syncthreads();

        const float* As = sm + cur * 2 * TILE_F;
        const float* Ws = As + TILE_F;
        const int pa = (wm + g) * SSTR + tg;
        const int pb = (wn + g) * SSTR + tg;

#pragma unroll
        for (int kk = 0; kk < 4; kk++) {
            uint32_t af[4][4], bf[4][2];
#pragma unroll
            for (int mt = 0; mt < 4; mt++) {
                const int ib = pa + mt * 16 * SSTR + kk * 8;
                af[mt][0] = f2tf32(As[ib]);
                af[mt][1] = f2tf32(As[ib + 8 * SSTR]);
                af[mt][2] = f2tf32(As[ib + 4]);
                af[mt][3] = f2tf32(As[ib + 8 * SSTR + 4]);
            }
#pragma unroll
            for (int nt = 0; nt < 4; nt++) {
                const int ib = pb + nt * 8 * SSTR + kk * 8;
                bf[nt][0] = f2tf32(Ws[ib]);
                bf[nt][1] = f2tf32(Ws[ib + 4]);
            }
#pragma unroll
            for (int mt = 0; mt < 4; mt++)
#pragma unroll
                for (int nt = 0; nt < 4; nt++)
                    mma_tf32(acc[mt][nt], af[mt], bf[nt]);
        }
        __syncthreads();
    }

#pragma unroll
    for (int mt = 0; mt < 4; mt++) {
#pragma unroll
        for (int nt = 0; nt < 4; nt++) {
            const int row = brow + wm + mt * 16 + g;
            const int col = bcol + wn + nt * 8 + 2 * tg;
            float b0 = 0.f, b1 = 0.f;
            if (bias) { b0 = bias[col]; b1 = bias[col + 1]; }
            *(float2*)(C + (long)row * EE + col) =
                make_float2(acc[mt][nt][0] + b0, acc[mt][nt][1] + b1);
            *(float2*)(C + (long)(row + 8) * EE + col) =
                make_float2(acc[mt][nt][2] + b0, acc[mt][nt][3] + b1);
        }
    }
}

// Fused QKV projection: grid (24, 64). blockIdx.x>>3 selects matrix.
__global__ void __launch_bounds__(256)
gemm_qkv(const float* __restrict__ A,
         const float* __restrict__ Wq, const float* __restrict__ Wk,
         const float* __restrict__ Wv,
         float* __restrict__ Cq, float* __restrict__ Ck, float* __restrict__ Cv)
{
    extern __shared__ float sm[];
    const int sel  = blockIdx.x >> 3;
    const int bcol = (blockIdx.x & 7) * 128;
    const int brow = blockIdx.y * 128;
    const float* W = (sel == 0) ? Wq : (sel == 1) ? Wk : Wv;
    float*       C = (sel == 0) ? Cq : (sel == 1) ? Ck : Cv;
    gemm_body(A, W, nullptr, C, brow, bcol, sm, smem_u32(sm));
}

// Single GEMM (output projection, +bias)
__global__ void __launch_bounds__(256)
gemm_tf32(const float* __restrict__ A, const float* __restrict__ W,
          const float* __restrict__ bias, float* __restrict__ C)
{
    extern __shared__ float sm[];
    gemm_body(A, W, bias, C, blockIdx.y * 128, blockIdx.x * 128, sm, smem_u32(sm));
}

// ---------------------------------------------------------------------------
// Tensor-core flash attention (R6 verbatim): 2-stage KV, in-loop cvt.
// Block: 128 q-rows, 8 warps x 16 rows. KV tiles of 64.
// ---------------------------------------------------------------------------
#define KSTR 68
#define VSTR 72
#define KVBUF (64 * KSTR + 64 * VSTR)           // 8960 floats per buffer
#define NEG_BIG (-1e30f)
#define FLASH_SMEMF (2 * KVBUF + 8 * 16 * KSTR) // 26624 floats = 106496 B

__global__ void __launch_bounds__(256, 2)
flash_tc(const float* __restrict__ Qg, const float* __restrict__ Kg,
         const float* __restrict__ Vg, float* __restrict__ Og)
{
    extern __shared__ float smem[];
    float* Qs = smem;                        // [128][KSTR] staging (over KV bufs)
    float* Ps = smem + 2 * KVBUF;

    const uint32_t smb = smem_u32(smem);
    const int tid = threadIdx.x;
    const int w = tid >> 5, lane = tid & 31;
    const int g = lane >> 2, tg = lane & 3;
    const int qt = blockIdx.x;
    const int b = blockIdx.y / HH, h = blockIdx.y % HH;
    const int wm = w * 16;
    const int qlo = qt * 128 + wm;

    const float* Qb = Qg + (long)b * SS * EE + h * DD;
    const float* Kb = Kg + (long)b * SS * EE + h * DD;
    const float* Vb = Vg + (long)b * SS * EE + h * DD;
    float*       Ob = Og + (long)b * SS * EE + h * DD;

    // ---- stage Q tile raw, extract scaled tf32 fragments ----
    {
        const int r = tid >> 1, c = (tid & 1) * 32;
        const float* src = Qb + (long)(qt * 128 + r) * EE + c;
        const uint32_t dst = smb + (r * KSTR + c) * 4;
#pragma unroll
        for (int j = 0; j < 8; j++) cp_async16(dst + j * 16, src + j * 4);
        CP_COMMIT(); CP_WAIT(0);
    }
    __syncthreads();

    uint32_t qf[8][4];
    const float sc = 0.03125f;   // 1/sqrt(1024) folded into Q
#pragma unroll
    for (int ks = 0; ks < 8; ks++) {
        qf[ks][0] = f2tf32(Qs[(wm + g)     * KSTR + tg     + 8 * ks] * sc);
        qf[ks][1] = f2tf32(Qs[(wm + g + 8) * KSTR + tg     + 8 * ks] * sc);
        qf[ks][2] = f2tf32(Qs[(wm + g)     * KSTR + tg + 4 + 8 * ks] * sc);
        qf[ks][3] = f2tf32(Qs[(wm + g + 8) * KSTR + tg + 4 + 8 * ks] * sc);
    }
    __syncthreads();

    float of[8][4];
#pragma unroll
    for (int i = 0; i < 8; i++)
#pragma unroll
        for (int j = 0; j < 4; j++) of[i][j] = 0.f;
    float m0 = NEG_BIG, m1 = NEG_BIG, l0 = 0.f, l1 = 0.f;
    float* Pw = Ps + w * 16 * KSTR;

    const int lr = tid >> 2, lc = (tid & 3) * 16;
    const int ntiles = 2 * qt + 2;

    // prologue: tile 0 -> buf 0
    {
        const float* ksrc = Kb + (long)lr * EE + lc;
        const float* vsrc = Vb + (long)lr * EE + lc;
        const uint32_t kdst = smb + (lr * KSTR + lc) * 4;
        const uint32_t vdst = smb + (64 * KSTR + lr * VSTR + lc) * 4;
#pragma unroll
        for (int j = 0; j < 4; j++) cp_async16(kdst + j * 16, ksrc + j * 4);
#pragma unroll
        for (int j = 0; j < 4; j++) cp_async16(vdst + j * 16, vsrc + j * 4);
        CP_COMMIT();
    }

    for (int kt = 0; kt < ntiles; kt++) {
        const int cur = kt & 1, nxt = cur ^ 1;

        if (kt + 1 < ntiles) {
            const long roff = (long)((kt + 1) * 64 + lr) * EE + lc;
            const uint32_t kdst = smb + (nxt * KVBUF + lr * KSTR + lc) * 4;
            const uint32_t vdst = smb + (nxt * KVBUF + 64 * KSTR + lr * VSTR + lc) * 4;
#pragma unroll
            for (int j = 0; j < 4; j++) cp_async16(kdst + j * 16, Kb + roff + j * 4);
#pragma unroll
            for (int j = 0; j < 4; j++) cp_async16(vdst + j * 16, Vb + roff + j * 4);
            CP_COMMIT();
            CP_WAIT(1);
        } else {
            CP_WAIT(0);
        }
        __syncthreads();

        const float* Ks = smem + cur * KVBUF;
        const float* Vs = Ks + 64 * KSTR;

        if (kt * 64 <= qlo + 15) {
            // ---- S = Q K^T ----
            float s[8][4];
#pragma unroll
            for (int nt = 0; nt < 8; nt++) {
                float c4[4] = {0.f, 0.f, 0.f, 0.f};
#pragma unroll
                for (int ks = 0; ks < 8; ks++) {
                    uint32_t bb[2];
                    bb[0] = f2tf32(Ks[(nt * 8 + g) * KSTR + tg     + 8 * ks]);
                    bb[1] = f2tf32(Ks[(nt * 8 + g) * KSTR + tg + 4 + 8 * ks]);
                    mma_tf32(c4, qf[ks], bb);
                }
                s[nt][0] = c4[0]; s[nt][1] = c4[1]; s[nt][2] = c4[2]; s[nt][3] = c4[3];
            }

            // ---- causal mask ----
            if (kt * 64 + 63 > qlo) {
                const int r0g = qlo + g, r1g = qlo + g + 8;
#pragma unroll
                for (int nt = 0; nt < 8; nt++) {
                    const int col = kt * 64 + nt * 8 + 2 * tg;
                    if (col     > r0g) s[nt][0] = NEG_BIG;
                    if (col + 1 > r0g) s[nt][1] = NEG_BIG;
                    if (col     > r1g) s[nt][2] = NEG_BIG;
                    if (col + 1 > r1g) s[nt][3] = NEG_BIG;
                }
            }

            // ---- online softmax ----
            float a0 = NEG_BIG, a1 = NEG_BIG;
#pragma unroll
            for (int nt = 0; nt < 8; nt++) {
                a0 = fmaxf(a0, fmaxf(s[nt][0], s[nt][1]));
                a1 = fmaxf(a1, fmaxf(s[nt][2], s[nt][3]));
            }
            a0 = fmaxf(a0, __shfl_xor_sync(0xffffffffu, a0, 1));
            a0 = fmaxf(a0, __shfl_xor_sync(0xffffffffu, a0, 2));
            a1 = fmaxf(a1, __shfl_xor_sync(0xffffffffu, a1, 1));
            a1 = fmaxf(a1, __shfl_xor_sync(0xffffffffu, a1, 2));

            const float mn0 = fmaxf(m0, a0), mn1 = fmaxf(m1, a1);
            const float cf0 = __expf(m0 - mn0), cf1 = __expf(m1 - mn1);
            m0 = mn0; m1 = mn1;

            float sum0 = 0.f, sum1 = 0.f;
#pragma unroll
            for (int nt = 0; nt < 8; nt++) {
                float p0 = __expf(s[nt][0] - m0);
                float p1 = __expf(s[nt][1] - m0);
                float p2 = __expf(s[nt][2] - m1);
                float p3 = __expf(s[nt][3] - m1);
                sum0 += p0 + p1; sum1 += p2 + p3;
                *(float2*)&Pw[g       * KSTR + nt * 8 + 2 * tg] = make_float2(p0, p1);
                *(float2*)&Pw[(g + 8) * KSTR + nt * 8 + 2 * tg] = make_float2(p2, p3);
            }
            sum0 += __shfl_xor_sync(0xffffffffu, sum0, 1);
            sum0 += __shfl_xor_sync(0xffffffffu, sum0, 2);
            sum1 += __shfl_xor_sync(0xffffffffu, sum1, 1);
            sum1 += __shfl_xor_sync(0xffffffffu, sum1, 2);
            l0 = l0 * cf0 + sum0;
            l1 = l1 * cf1 + sum1;
#pragma unroll
            for (int nt = 0; nt < 8; nt++) {
                of[nt][0] *= cf0; of[nt][1] *= cf0;
                of[nt][2] *= cf1; of[nt][3] *= cf1;
            }
            __syncwarp();

            // ---- O += P V ----
#pragma unroll
            for (int ks = 0; ks < 8; ks++) {
                uint32_t af[4];
                af[0] = f2tf32(Pw[g       * KSTR + tg     + 8 * ks]);
                af[1] = f2tf32(Pw[(g + 8) * KSTR + tg     + 8 * ks]);
                af[2] = f2tf32(Pw[g       * KSTR + tg + 4 + 8 * ks]);
                af[3] = f2tf32(Pw[(g + 8) * KSTR + tg + 4 + 8 * ks]);
#pragma unroll
                for (int dn = 0; dn < 8; dn++) {
                    uint32_t bb[2];
                    bb[0] = f2tf32(Vs[(tg     + 8 * ks) * VSTR + dn * 8 + g]);
                    bb[1] = f2tf32(Vs[(tg + 4 + 8 * ks) * VSTR + dn * 8 + g]);
                    mma_tf32(of[dn], af, bb);
                }
            }
        }
        __syncthreads();
    }

    // ---- epilogue ----
    const float i0 = 1.f / l0, i1 = 1.f / l1;
    const int r0g = qt * 128 + wm + g, r1g = r0g + 8;
#pragma unroll
    for (int dn = 0; dn < 8; dn++) {
        const int col = dn * 8 + 2 * tg;
        *(float2*)(Ob + (long)r0g * EE + col) =
            make_float2(of[dn][0] * i0, of[dn][1] * i0);
        *(float2*)(Ob + (long)r1g * EE + col) =
            make_float2(of[dn][2] * i1, of[dn][3] * i1);
    }
}

// ---------------------------------------------------------------------------
extern "C" void kernel_launch(void* const* d_in, const int* in_sizes, int n_in,
                              void* d_out, int out_size)
{
    const float* x  = (const float*)d_in[0];
    const float* Wq = (const float*)d_in[1];
    const float* Wk = (const float*)d_in[2];
    const float* Wv = (const float*)d_in[3];
    const float* Wo = (const float*)d_in[4];
    const float* bo = (const float*)d_in[5];
    float* out = (float*)d_out;

    float *q, *k, *v, *a;
    cudaGetSymbolAddress((void**)&q, g_q);
    cudaGetSymbolAddress((void**)&k, g_k);
    cudaGetSymbolAddress((void**)&v, g_v);
    cudaGetSymbolAddress((void**)&a, g_attn);

    const int gemm_smem = 4 * TILE_F * sizeof(float);   // 73728 B
    cudaFuncSetAttribute(gemm_qkv,
                         cudaFuncAttributeMaxDynamicSharedMemorySize, gemm_smem);
    cudaFuncSetAttribute(gemm_tf32,
                         cudaFuncAttributeMaxDynamicSharedMemorySize, gemm_smem);

    // fused QKV projection: one kernel, 24x64 grid
    gemm_qkv<<<dim3(24, BSROWS / 128), 256, gemm_smem>>>(x, Wq, Wk, Wv, q, k, v);

    const int flash_smem = FLASH_SMEMF * sizeof(float);  // 106496 B
    cudaFuncSetAttribute(flash_tc,
                         cudaFuncAttributeMaxDynamicSharedMemorySize, flash_smem);
    flash_tc<<<dim3(SS / 128, BB * HH), 256, flash_smem>>>(q, k, v, a);

    gemm_tf32<<<dim3(EE / 128, BSROWS / 128), 256, gemm_smem>>>(a, Wo, bo, out);
}

// round 11
// speedup vs baseline: 1.4758x; 1.3740x over previous
#include <cuda_runtime.h>
#include <cuda_bf16.h>
#include <cuda_fp16.h>
#include <cstdint>

#define BB 4
#define SS 2048
#define EE 1024
#define HH 16
#define DD 64
#define BSROWS (BB * SS)   // 8192

// Scratch (device globals; allocation-free per harness rules).
__device__ float  g_q[BSROWS * EE];
__device__ float  g_k[BSROWS * EE];
__device__ float  g_v[BSROWS * EE];
__device__ __half g_ah[BSROWS * EE];        // attention output (fp16, feeds Wo)
__device__ __half g_xh[BSROWS * EE];
__device__ __half g_wqh[EE * EE];
__device__ __half g_wkh[EE * EE];
__device__ __half g_wvh[EE * EE];
__device__ __half g_woh[EE * EE];

// ---------------------------------------------------------------------------
// helpers
// ---------------------------------------------------------------------------
__device__ __forceinline__ uint32_t smem_u32(const void* p) {
    uint32_t a;
    asm("{ .reg .u64 t; cvta.to.shared.u64 t, %1; cvt.u32.u64 %0, t; }" : "=r"(a) : "l"(p));
    return a;
}
__device__ __forceinline__ uint32_t f2tf32(float f) {
    uint32_t r;
    asm("cvt.rna.tf32.f32 %0, %1;" : "=r"(r) : "f"(f));
    return r;
}
__device__ __forceinline__ void cp_async16(uint32_t dst, const void* src) {
    asm volatile("cp.async.ca.shared.global [%0], [%1], 16;" :: "r"(dst), "l"(src));
}
#define CP_COMMIT() asm volatile("cp.async.commit_group;" ::: "memory")
#define CP_WAIT(n)  asm volatile("cp.async.wait_group %0;" :: "n"(n) : "memory")

__device__ __forceinline__ void mma_tf32(float* c, const uint32_t* a, const uint32_t* b) {
    asm volatile(
        "mma.sync.aligned.m16n8k8.row.col.f32.tf32.tf32.f32 "
        "{%0,%1,%2,%3}, {%4,%5,%6,%7}, {%8,%9}, {%0,%1,%2,%3};"
        : "+f"(c[0]), "+f"(c[1]), "+f"(c[2]), "+f"(c[3])
        : "r"(a[0]), "r"(a[1]), "r"(a[2]), "r"(a[3]), "r"(b[0]), "r"(b[1]));
}
__device__ __forceinline__ void mma_f16(float* c, const uint32_t* a, const uint32_t* b) {
    asm volatile(
        "mma.sync.aligned.m16n8k16.row.col.f32.f16.f16.f32 "
        "{%0,%1,%2,%3}, {%4,%5,%6,%7}, {%8,%9}, {%0,%1,%2,%3};"
        : "+f"(c[0]), "+f"(c[1]), "+f"(c[2]), "+f"(c[3])
        : "r"(a[0]), "r"(a[1]), "r"(a[2]), "r"(a[3]), "r"(b[0]), "r"(b[1]));
}

// ---------------------------------------------------------------------------
// prep: fp32 -> fp16 GMEM (bandwidth-bound)
// ---------------------------------------------------------------------------
__global__ void prep_h(const float* __restrict__ src, __half* __restrict__ dst, int n4)
{
    int i = blockIdx.x * blockDim.x + threadIdx.x;
    if (i >= n4) return;
    float4 a = ((const float4*)src)[i];
    __half2* d = (__half2*)dst + 2 * i;
    d[0] = __floats2half2_rn(a.x, a.y);
    d[1] = __floats2half2_rn(a.z, a.w);
}

// ---------------------------------------------------------------------------
// fp16 mma.sync GEMM: C[M,N](fp32) = A[M,K] * W[N,K]^T (+bias), A/W fp16.
// CTA 128x128, BK=64 (128B rows), 8 warps (2x4), warp tile 64x32, 2-stage.
// smem rows: 64 halves + 8 pad = 72 halves = 36 words (conflict-free: 4g+tg).
// ---------------------------------------------------------------------------
#define HST 72                      // halves per smem row
#define WST 36                      // words per smem row
#define TILE_W (128 * WST)          // words per matrix per stage (4608)
#define NCH 16                      // 1024 / 64

__device__ __forceinline__ void gemm_body_h(
    const __half* __restrict__ A, const __half* __restrict__ W,
    const float* __restrict__ bias, float* __restrict__ C,
    int brow, int bcol, uint32_t* smw, uint32_t smb)
{
    const int t    = threadIdx.x;
    const int lane = t & 31;
    const int w    = t >> 5;
    const int wm   = (w & 1) * 64;
    const int wn   = (w >> 1) * 32;
    const int g    = lane >> 2;
    const int tg   = lane & 3;

    // staging: thread t -> row t>>1, halves [(t&1)*32, +32)
    const int sr = t >> 1;
    const int sc = (t & 1) * 32;
    const __half* Ag = A + (long)(brow + sr) * EE + sc;
    const __half* Wg = W + (long)(bcol + sr) * EE + sc;
    const uint32_t sdA = smb + (sr * HST + sc) * 2;
    const uint32_t sdW = sdA + TILE_W * 4;

    float acc[4][4][4];
#pragma unroll
    for (int i = 0; i < 4; i++)
#pragma unroll
        for (int j = 0; j < 4; j++)
#pragma unroll
            for (int r = 0; r < 4; r++) acc[i][j][r] = 0.f;

#pragma unroll
    for (int j = 0; j < 4; j++) {
        cp_async16(sdA + j * 16, Ag + j * 8);
        cp_async16(sdW + j * 16, Wg + j * 8);
    }
    CP_COMMIT();

    for (int kc = 0; kc < NCH; kc++) {
        const int cur = kc & 1, nxt = cur ^ 1;

        if (kc + 1 < NCH) {
            const int k0 = (kc + 1) * 64;
            const uint32_t bofs = nxt * 2 * TILE_W * 4;
#pragma unroll
            for (int j = 0; j < 4; j++) {
                cp_async16(sdA + bofs + j * 16, Ag + k0 + j * 8);
                cp_async16(sdW + bofs + j * 16, Wg + k0 + j * 8);
            }
            CP_COMMIT();
            CP_WAIT(1);
        } else {
            CP_WAIT(0);
        }
        __syncthreads();

        const uint32_t* As = smw + cur * 2 * TILE_W;
        const uint32_t* Ws = As + TILE_W;

#pragma unroll
        for (int ks = 0; ks < 4; ks++) {
            uint32_t af[4][4], bf[4][2];
#pragma unroll
            for (int mt = 0; mt < 4; mt++) {
                const int ib = (wm + mt * 16 + g) * WST + ks * 8 + tg;
                af[mt][0] = As[ib];
                af[mt][1] = As[ib + 8 * WST];
                af[mt][2] = As[ib + 4];
                af[mt][3] = As[ib + 8 * WST + 4];
            }
#pragma unroll
            for (int nt = 0; nt < 4; nt++) {
                const int ib = (wn + nt * 8 + g) * WST + ks * 8 + tg;
                bf[nt][0] = Ws[ib];
                bf[nt][1] = Ws[ib + 4];
            }
#pragma unroll
            for (int mt = 0; mt < 4; mt++)
#pragma unroll
                for (int nt = 0; nt < 4; nt++)
                    mma_f16(acc[mt][nt], af[mt], bf[nt]);
        }
        __syncthreads();
    }

#pragma unroll
    for (int mt = 0; mt < 4; mt++) {
#pragma unroll
        for (int nt = 0; nt < 4; nt++) {
            const int row = brow + wm + mt * 16 + g;
            const int col = bcol + wn + nt * 8 + 2 * tg;
            float b0 = 0.f, b1 = 0.f;
            if (bias) { b0 = bias[col]; b1 = bias[col + 1]; }
            *(float2*)(C + (long)row * EE + col) =
                make_float2(acc[mt][nt][0] + b0, acc[mt][nt][1] + b1);
            *(float2*)(C + (long)(row + 8) * EE + col) =
                make_float2(acc[mt][nt][2] + b0, acc[mt][nt][3] + b1);
        }
    }
}

// Fused QKV projection: grid (24, 64). blockIdx.x>>3 selects matrix.
__global__ void __launch_bounds__(256)
gemm_qkv_h(const __half* __restrict__ A,
           const __half* __restrict__ Wq, const __half* __restrict__ Wk,
           const __half* __restrict__ Wv,
           float* __restrict__ Cq, float* __restrict__ Ck, float* __restrict__ Cv)
{
    extern __shared__ uint32_t smw[];
    const int sel  = blockIdx.x >> 3;
    const int bcol = (blockIdx.x & 7) * 128;
    const int brow = blockIdx.y * 128;
    const __half* W = (sel == 0) ? Wq : (sel == 1) ? Wk : Wv;
    float*        C = (sel == 0) ? Cq : (sel == 1) ? Ck : Cv;
    gemm_body_h(A, W, nullptr, C, brow, bcol, smw, smem_u32(smw));
}

// Output projection (+bias)
__global__ void __launch_bounds__(256)
gemm_h(const __half* __restrict__ A, const __half* __restrict__ W,
       const float* __restrict__ bias, float* __restrict__ C)
{
    extern __shared__ uint32_t smw[];
    gemm_body_h(A, W, bias, C, blockIdx.y * 128, blockIdx.x * 128, smw, smem_u32(smw));
}

// ---------------------------------------------------------------------------
// Tensor-core flash attention (R6 verbatim, tf32): 2-stage KV, in-loop cvt.
// Only change: output written as fp16 (feeds the fp16 Wo GEMM).
// ---------------------------------------------------------------------------
#define KSTR 68
#define VSTR 72
#define KVBUF (64 * KSTR + 64 * VSTR)           // 8960 floats per buffer
#define NEG_BIG (-1e30f)
#define FLASH_SMEMF (2 * KVBUF + 8 * 16 * KSTR) // 26624 floats = 106496 B

__global__ void __launch_bounds__(256, 2)
flash_tc(const float* __restrict__ Qg, const float* __restrict__ Kg,
         const float* __restrict__ Vg, __half* __restrict__ Og)
{
    extern __shared__ float smem[];
    float* Qs = smem;                        // [128][KSTR] staging (over KV bufs)
    float* Ps = smem + 2 * KVBUF;

    const uint32_t smb = smem_u32(smem);
    const int tid = threadIdx.x;
    const int w = tid >> 5, lane = tid & 31;
    const int g = lane >> 2, tg = lane & 3;
    const int qt = blockIdx.x;
    const int b = blockIdx.y / HH, h = blockIdx.y % HH;
    const int wm = w * 16;
    const int qlo = qt * 128 + wm;

    const float* Qb = Qg + (long)b * SS * EE + h * DD;
    const float* Kb = Kg + (long)b * SS * EE + h * DD;
    const float* Vb = Vg + (long)b * SS * EE + h * DD;
    __half*      Ob = Og + (long)b * SS * EE + h * DD;

    // ---- stage Q tile raw, extract scaled tf32 fragments ----
    {
        const int r = tid >> 1, c = (tid & 1) * 32;
        const float* src = Qb + (long)(qt * 128 + r) * EE + c;
        const uint32_t dst = smb + (r * KSTR + c) * 4;
#pragma unroll
        for (int j = 0; j < 8; j++) cp_async16(dst + j * 16, src + j * 4);
        CP_COMMIT(); CP_WAIT(0);
    }
    __syncthreads();

    uint32_t qf[8][4];
    const float sc = 0.03125f;   // 1/sqrt(1024) folded into Q
#pragma unroll
    for (int ks = 0; ks < 8; ks++) {
        qf[ks][0] = f2tf32(Qs[(wm + g)     * KSTR + tg     + 8 * ks] * sc);
        qf[ks][1] = f2tf32(Qs[(wm + g + 8) * KSTR + tg     + 8 * ks] * sc);
        qf[ks][2] = f2tf32(Qs[(wm + g)     * KSTR + tg + 4 + 8 * ks] * sc);
        qf[ks][3] = f2tf32(Qs[(wm + g + 8) * KSTR + tg + 4 + 8 * ks] * sc);
    }
    __syncthreads();

    float of[8][4];
#pragma unroll
    for (int i = 0; i < 8; i++)
#pragma unroll
        for (int j = 0; j < 4; j++) of[i][j] = 0.f;
    float m0 = NEG_BIG, m1 = NEG_BIG, l0 = 0.f, l1 = 0.f;
    float* Pw = Ps + w * 16 * KSTR;

    const int lr = tid >> 2, lc = (tid & 3) * 16;
    const int ntiles = 2 * qt + 2;

    // prologue: tile 0 -> buf 0
    {
        const float* ksrc = Kb + (long)lr * EE + lc;
        const float* vsrc = Vb + (long)lr * EE + lc;
        const uint32_t kdst = smb + (lr * KSTR + lc) * 4;
        const uint32_t vdst = smb + (64 * KSTR + lr * VSTR + lc) * 4;
#pragma unroll
        for (int j = 0; j < 4; j++) cp_async16(kdst + j * 16, ksrc + j * 4);
#pragma unroll
        for (int j = 0; j < 4; j++) cp_async16(vdst + j * 16, vsrc + j * 4);
        CP_COMMIT();
    }

    for (int kt = 0; kt < ntiles; kt++) {
        const int cur = kt & 1, nxt = cur ^ 1;

        if (kt + 1 < ntiles) {
            const long roff = (long)((kt + 1) * 64 + lr) * EE + lc;
            const uint32_t kdst = smb + (nxt * KVBUF + lr * KSTR + lc) * 4;
            const uint32_t vdst = smb + (nxt * KVBUF + 64 * KSTR + lr * VSTR + lc) * 4;
#pragma unroll
            for (int j = 0; j < 4; j++) cp_async16(kdst + j * 16, Kb + roff + j * 4);
#pragma unroll
            for (int j = 0; j < 4; j++) cp_async16(vdst + j * 16, Vb + roff + j * 4);
            CP_COMMIT();
            CP_WAIT(1);
        } else {
            CP_WAIT(0);
        }
        __syncthreads();

        const float* Ks = smem + cur * KVBUF;
        const float* Vs = Ks + 64 * KSTR;

        if (kt * 64 <= qlo + 15) {
            // ---- S = Q K^T ----
            float s[8][4];
#pragma unroll
            for (int nt = 0; nt < 8; nt++) {
                float c4[4] = {0.f, 0.f, 0.f, 0.f};
#pragma unroll
                for (int ks = 0; ks < 8; ks++) {
                    uint32_t bb[2];
                    bb[0] = f2tf32(Ks[(nt * 8 + g) * KSTR + tg     + 8 * ks]);
                    bb[1] = f2tf32(Ks[(nt * 8 + g) * KSTR + tg + 4 + 8 * ks]);
                    mma_tf32(c4, qf[ks], bb);
                }
                s[nt][0] = c4[0]; s[nt][1] = c4[1]; s[nt][2] = c4[2]; s[nt][3] = c4[3];
            }

            // ---- causal mask ----
            if (kt * 64 + 63 > qlo) {
                const int r0g = qlo + g, r1g = qlo + g + 8;
#pragma unroll
                for (int nt = 0; nt < 8; nt++) {
                    const int col = kt * 64 + nt * 8 + 2 * tg;
                    if (col     > r0g) s[nt][0] = NEG_BIG;
                    if (col + 1 > r0g) s[nt][1] = NEG_BIG;
                    if (col     > r1g) s[nt][2] = NEG_BIG;
                    if (col + 1 > r1g) s[nt][3] = NEG_BIG;
                }
            }

            // ---- online softmax ----
            float a0 = NEG_BIG, a1 = NEG_BIG;
#pragma unroll
            for (int nt = 0; nt < 8; nt++) {
                a0 = fmaxf(a0, fmaxf(s[nt][0], s[nt][1]));
                a1 = fmaxf(a1, fmaxf(s[nt][2], s[nt][3]));
            }
            a0 = fmaxf(a0, __shfl_xor_sync(0xffffffffu, a0, 1));
            a0 = fmaxf(a0, __shfl_xor_sync(0xffffffffu, a0, 2));
            a1 = fmaxf(a1, __shfl_xor_sync(0xffffffffu, a1, 1));
            a1 = fmaxf(a1, __shfl_xor_sync(0xffffffffu, a1, 2));

            const float mn0 = fmaxf(m0, a0), mn1 = fmaxf(m1, a1);
            const float cf0 = __expf(m0 - mn0), cf1 = __expf(m1 - mn1);
            m0 = mn0; m1 = mn1;

            float sum0 = 0.f, sum1 = 0.f;
#pragma unroll
            for (int nt = 0; nt < 8; nt++) {
                float p0 = __expf(s[nt][0] - m0);
                float p1 = __expf(s[nt][1] - m0);
                float p2 = __expf(s[nt][2] - m1);
                float p3 = __expf(s[nt][3] - m1);
                sum0 += p0 + p1; sum1 += p2 + p3;
                *(float2*)&Pw[g       * KSTR + nt * 8 + 2 * tg] = make_float2(p0, p1);
                *(float2*)&Pw[(g + 8) * KSTR + nt * 8 + 2 * tg] = make_float2(p2, p3);
            }
            sum0 += __shfl_xor_sync(0xffffffffu, sum0, 1);
            sum0 += __shfl_xor_sync(0xffffffffu, sum0, 2);
            sum1 += __shfl_xor_sync(0xffffffffu, sum1, 1);
            sum1 += __shfl_xor_sync(0xffffffffu, sum1, 2);
            l0 = l0 * cf0 + sum0;
            l1 = l1 * cf1 + sum1;
#pragma unroll
            for (int nt = 0; nt < 8; nt++) {
                of[nt][0] *= cf0; of[nt][1] *= cf0;
                of[nt][2] *= cf1; of[nt][3] *= cf1;
            }
            __syncwarp();

            // ---- O += P V ----
#pragma unroll
            for (int ks = 0; ks < 8; ks++) {
                uint32_t af[4];
                af[0] = f2tf32(Pw[g       * KSTR + tg     + 8 * ks]);
                af[1] = f2tf32(Pw[(g + 8) * KSTR + tg     + 8 * ks]);
                af[2] = f2tf32(Pw[g       * KSTR + tg + 4 + 8 * ks]);
                af[3] = f2tf32(Pw[(g + 8) * KSTR + tg + 4 + 8 * ks]);
#pragma unroll
                for (int dn = 0; dn < 8; dn++) {
                    uint32_t bb[2];
                    bb[0] = f2tf32(Vs[(tg     + 8 * ks) * VSTR + dn * 8 + g]);
                    bb[1] = f2tf32(Vs[(tg + 4 + 8 * ks) * VSTR + dn * 8 + g]);
                    mma_tf32(of[dn], af, bb);
                }
            }
        }
        __syncthreads();
    }

    // ---- epilogue: normalize, store fp16 ----
    const float i0 = 1.f / l0, i1 = 1.f / l1;
    const int r0g = qt * 128 + wm + g, r1g = r0g + 8;
#pragma unroll
    for (int dn = 0; dn < 8; dn++) {
        const int col = dn * 8 + 2 * tg;
        *(__half2*)(Ob + (long)r0g * EE + col) =
            __floats2half2_rn(of[dn][0] * i0, of[dn][1] * i0);
        *(__half2*)(Ob + (long)r1g * EE + col) =
            __floats2half2_rn(of[dn][2] * i1, of[dn][3] * i1);
    }
}

// ---------------------------------------------------------------------------
extern "C" void kernel_launch(void* const* d_in, const int* in_sizes, int n_in,
                              void* d_out, int out_size)
{
    const float* x  = (const float*)d_in[0];
    const float* Wq = (const float*)d_in[1];
    const float* Wk = (const float*)d_in[2];
    const float* Wv = (const float*)d_in[3];
    const float* Wo = (const float*)d_in[4];
    const float* bo = (const float*)d_in[5];
    float* out = (float*)d_out;

    float *q, *k, *v;
    __half *ah, *xh, *wqh, *wkh, *wvh, *woh;
    cudaGetSymbolAddress((void**)&q,   g_q);
    cudaGetSymbolAddress((void**)&k,   g_k);
    cudaGetSymbolAddress((void**)&v,   g_v);
    cudaGetSymbolAddress((void**)&ah,  g_ah);
    cudaGetSymbolAddress((void**)&xh,  g_xh);
    cudaGetSymbolAddress((void**)&wqh, g_wqh);
    cudaGetSymbolAddress((void**)&wkh, g_wkh);
    cudaGetSymbolAddress((void**)&wvh, g_wvh);
    cudaGetSymbolAddress((void**)&woh, g_woh);

    // prep: fp32 -> fp16
    const int xn4 = BSROWS * EE / 4, wn4 = EE * EE / 4;
    prep_h<<<(xn4 + 255) / 256, 256>>>(x,  xh,  xn4);
    prep_h<<<(wn4 + 255) / 256, 256>>>(Wq, wqh, wn4);
    prep_h<<<(wn4 + 255) / 256, 256>>>(Wk, wkh, wn4);
    prep_h<<<(wn4 + 255) / 256, 256>>>(Wv, wvh, wn4);
    prep_h<<<(wn4 + 255) / 256, 256>>>(Wo, woh, wn4);

    const int gemm_smem = 4 * TILE_W * sizeof(uint32_t);   // 73728 B
    cudaFuncSetAttribute(gemm_qkv_h,
                         cudaFuncAttributeMaxDynamicSharedMemorySize, gemm_smem);
    cudaFuncSetAttribute(gemm_h,
                         cudaFuncAttributeMaxDynamicSharedMemorySize, gemm_smem);

    // fused QKV projection (fp16 in, fp32 out)
    gemm_qkv_h<<<dim3(24, BSROWS / 128), 256, gemm_smem>>>(xh, wqh, wkh, wvh, q, k, v);

    const int flash_smem = FLASH_SMEMF * sizeof(float);  // 106496 B
    cudaFuncSetAttribute(flash_tc,
                         cudaFuncAttributeMaxDynamicSharedMemorySize, flash_smem);
    flash_tc<<<dim3(SS / 128, BB * HH), 256, flash_smem>>>(q, k, v, ah);

    // output projection (fp16 in, fp32 out + bias)
    gemm_h<<<dim3(EE / 128, BSROWS / 128), 256, gemm_smem>>>(ah, woh, bo, out);
}

// round 12
// speedup vs baseline: 2.2660x; 1.5354x over previous
#include <cuda_runtime.h>
#include <cuda_bf16.h>
#include <cuda_fp16.h>
#include <cstdint>

#define BB 4
#define SS 2048
#define EE 1024
#define HH 16
#define DD 64
#define BSROWS (BB * SS)   // 8192

// Scratch (device globals; allocation-free per harness rules).
__device__ __half g_qh[BSROWS * EE];        // Q, fp16, pre-scaled by 1/32
__device__ __half g_kh[BSROWS * EE];        // K, fp16, row-major
__device__ __half g_vt[BSROWS * EE];        // V^T, fp16, [b][h][d][s]
__device__ __half g_ah[BSROWS * EE];        // attention out (fp16, feeds Wo)
__device__ __half g_xh[BSROWS * EE];
__device__ __half g_wqh[EE * EE];
__device__ __half g_wkh[EE * EE];
__device__ __half g_wvh[EE * EE];
__device__ __half g_woh[EE * EE];

// ---------------------------------------------------------------------------
// helpers
// ---------------------------------------------------------------------------
__device__ __forceinline__ uint32_t smem_u32(const void* p) {
    uint32_t a;
    asm("{ .reg .u64 t; cvta.to.shared.u64 t, %1; cvt.u32.u64 %0, t; }" : "=r"(a) : "l"(p));
    return a;
}
__device__ __forceinline__ void cp_async16(uint32_t dst, const void* src) {
    asm volatile("cp.async.ca.shared.global [%0], [%1], 16;" :: "r"(dst), "l"(src));
}
#define CP_COMMIT() asm volatile("cp.async.commit_group;" ::: "memory")
#define CP_WAIT(n)  asm volatile("cp.async.wait_group %0;" :: "n"(n) : "memory")

__device__ __forceinline__ void mma_f16(float* c, const uint32_t* a, const uint32_t* b) {
    asm volatile(
        "mma.sync.aligned.m16n8k16.row.col.f32.f16.f16.f32 "
        "{%0,%1,%2,%3}, {%4,%5,%6,%7}, {%8,%9}, {%0,%1,%2,%3};"
        : "+f"(c[0]), "+f"(c[1]), "+f"(c[2]), "+f"(c[3])
        : "r"(a[0]), "r"(a[1]), "r"(a[2]), "r"(a[3]), "r"(b[0]), "r"(b[1]));
}

// ---------------------------------------------------------------------------
// prep: fp32 -> fp16 GMEM
// ---------------------------------------------------------------------------
__global__ void prep_h(const float* __restrict__ src, __half* __restrict__ dst, int n4)
{
    int i = blockIdx.x * blockDim.x + threadIdx.x;
    if (i >= n4) return;
    float4 a = ((const float4*)src)[i];
    __half2* d = (__half2*)dst + 2 * i;
    d[0] = __floats2half2_rn(a.x, a.y);
    d[1] = __floats2half2_rn(a.z, a.w);
}

// ---------------------------------------------------------------------------
// fp16 mma.sync GEMM: acc = A[M,K] * W[N,K]^T, A/W fp16, fp32 accum.
// CTA 128x128, BK=64, 8 warps (2x4), warp tile 64x32, 2-stage cp.async.
// Epilogue modes: 0 = fp32+bias, 1 = fp16 * (1/32) (Q), 2 = fp16 (K),
//                 3 = fp16 transposed [b][h][d][s] (V^T)
// ---------------------------------------------------------------------------
#define HST 72                      // halves per smem row
#define WST 36                      // words per smem row
#define TILE_W (128 * WST)          // words per matrix per stage
#define NCH 16                      // 1024 / 64

__device__ __forceinline__ void gemm_body_h(
    const __half* __restrict__ A, const __half* __restrict__ W,
    const float* __restrict__ bias, void* __restrict__ Cv,
    int brow, int bcol, uint32_t* smw, uint32_t smb, int mode)
{
    const int t    = threadIdx.x;
    const int lane = t & 31;
    const int w    = t >> 5;
    const int wm   = (w & 1) * 64;
    const int wn   = (w >> 1) * 32;
    const int g    = lane >> 2;
    const int tg   = lane & 3;

    const int sr = t >> 1;
    const int sc = (t & 1) * 32;
    const __half* Ag = A + (long)(brow + sr) * EE + sc;
    const __half* Wg = W + (long)(bcol + sr) * EE + sc;
    const uint32_t sdA = smb + (sr * HST + sc) * 2;
    const uint32_t sdW = sdA + TILE_W * 4;

    float acc[4][4][4];
#pragma unroll
    for (int i = 0; i < 4; i++)
#pragma unroll
        for (int j = 0; j < 4; j++)
#pragma unroll
            for (int r = 0; r < 4; r++) acc[i][j][r] = 0.f;

#pragma unroll
    for (int j = 0; j < 4; j++) {
        cp_async16(sdA + j * 16, Ag + j * 8);
        cp_async16(sdW + j * 16, Wg + j * 8);
    }
    CP_COMMIT();

    for (int kc = 0; kc < NCH; kc++) {
        const int cur = kc & 1, nxt = cur ^ 1;

        if (kc + 1 < NCH) {
            const int k0 = (kc + 1) * 64;
            const uint32_t bofs = nxt * 2 * TILE_W * 4;
#pragma unroll
            for (int j = 0; j < 4; j++) {
                cp_async16(sdA + bofs + j * 16, Ag + k0 + j * 8);
                cp_async16(sdW + bofs + j * 16, Wg + k0 + j * 8);
            }
            CP_COMMIT();
            CP_WAIT(1);
        } else {
            CP_WAIT(0);
        }
        __syncthreads();

        const uint32_t* As = smw + cur * 2 * TILE_W;
        const uint32_t* Ws = As + TILE_W;

#pragma unroll
        for (int ks = 0; ks < 4; ks++) {
            uint32_t af[4][4], bf[4][2];
#pragma unroll
            for (int mt = 0; mt < 4; mt++) {
                const int ib = (wm + mt * 16 + g) * WST + ks * 8 + tg;
                af[mt][0] = As[ib];
                af[mt][1] = As[ib + 8 * WST];
                af[mt][2] = As[ib + 4];
                af[mt][3] = As[ib + 8 * WST + 4];
            }
#pragma unroll
            for (int nt = 0; nt < 4; nt++) {
                const int ib = (wn + nt * 8 + g) * WST + ks * 8 + tg;
                bf[nt][0] = Ws[ib];
                bf[nt][1] = Ws[ib + 4];
            }
#pragma unroll
            for (int mt = 0; mt < 4; mt++)
#pragma unroll
                for (int nt = 0; nt < 4; nt++)
                    mma_f16(acc[mt][nt], af[mt], bf[nt]);
        }
        __syncthreads();
    }

    if (mode == 0) {
        float* C = (float*)Cv;
#pragma unroll
        for (int mt = 0; mt < 4; mt++)
#pragma unroll
            for (int nt = 0; nt < 4; nt++) {
                const int row = brow + wm + mt * 16 + g;
                const int col = bcol + wn + nt * 8 + 2 * tg;
                float b0 = bias ? bias[col] : 0.f;
                float b1 = bias ? bias[col + 1] : 0.f;
                *(float2*)(C + (long)row * EE + col) =
                    make_float2(acc[mt][nt][0] + b0, acc[mt][nt][1] + b1);
                *(float2*)(C + (long)(row + 8) * EE + col) =
                    make_float2(acc[mt][nt][2] + b0, acc[mt][nt][3] + b1);
            }
    } else if (mode == 3) {          // V^T: [b][h][d][s]
        __half* C = (__half*)Cv;
#pragma unroll
        for (int mt = 0; mt < 4; mt++)
#pragma unroll
            for (int nt = 0; nt < 4; nt++) {
                const int row = brow + wm + mt * 16 + g;
                const int col = bcol + wn + nt * 8 + 2 * tg;
                const int bi = row >> 11, s = row & (SS - 1);
                const int h = col >> 6, d = col & 63;
                const long base = ((long)(bi * HH + h) * DD + d) * SS + s;
                C[base]          = __float2half_rn(acc[mt][nt][0]);
                C[base + SS]     = __float2half_rn(acc[mt][nt][1]);
                C[base + 8]      = __float2half_rn(acc[mt][nt][2]);
                C[base + SS + 8] = __float2half_rn(acc[mt][nt][3]);
            }
    } else {                         // fp16 row-major (Q scaled / K)
        __half* C = (__half*)Cv;
        const float sc = (mode == 1) ? 0.03125f : 1.0f;
#pragma unroll
        for (int mt = 0; mt < 4; mt++)
#pragma unroll
            for (int nt = 0; nt < 4; nt++) {
                const int row = brow + wm + mt * 16 + g;
                const int col = bcol + wn + nt * 8 + 2 * tg;
                *(__half2*)(C + (long)row * EE + col) =
                    __floats2half2_rn(acc[mt][nt][0] * sc, acc[mt][nt][1] * sc);
                *(__half2*)(C + (long)(row + 8) * EE + col) =
                    __floats2half2_rn(acc[mt][nt][2] * sc, acc[mt][nt][3] * sc);
            }
    }
}

// Fused QKV projection: grid (24, 64). blockIdx.x>>3 selects matrix/mode.
__global__ void __launch_bounds__(256)
gemm_qkv_h(const __half* __restrict__ A,
           const __half* __restrict__ Wq, const __half* __restrict__ Wk,
           const __half* __restrict__ Wv,
           __half* __restrict__ Cq, __half* __restrict__ Ck, __half* __restrict__ Cv)
{
    extern __shared__ uint32_t smw[];
    const int sel  = blockIdx.x >> 3;
    const int bcol = (blockIdx.x & 7) * 128;
    const int brow = blockIdx.y * 128;
    const __half* W = (sel == 0) ? Wq : (sel == 1) ? Wk : Wv;
    void*         C = (sel == 0) ? (void*)Cq : (sel == 1) ? (void*)Ck : (void*)Cv;
    gemm_body_h(A, W, nullptr, C, brow, bcol, smw, smem_u32(smw), sel + 1);
}

// Output projection (+bias, fp32 out)
__global__ void __launch_bounds__(256)
gemm_h(const __half* __restrict__ A, const __half* __restrict__ W,
       const float* __restrict__ bias, float* __restrict__ C)
{
    extern __shared__ uint32_t smw[];
    gemm_body_h(A, W, bias, C, blockIdx.y * 128, blockIdx.x * 128,
                smw, smem_u32(smw), 0);
}

// ---------------------------------------------------------------------------
// fp16 tensor-core flash attention. Q pre-scaled fp16, K fp16 row-major,
// V^T fp16 [b][h][d][s]. 2-stage KV ring, m16n8k16 everywhere.
// smem (halves): KV stages 2 x (K 64x72 + Vt 64x72), P 8 warps x 16 x 72.
// ---------------------------------------------------------------------------
#define FH 72                                // halves per smem row
#define FW 36                                // words per smem row
#define KVH (64 * FH)                        // halves per K (or Vt) tile: 4608
#define KVBUF_H (2 * KVH)                    // halves per stage: 9216
#define NEG_BIG (-1e30f)
#define FLASH_SMEMH (2 * KVBUF_H + 8 * 16 * FH)   // 27648 halves = 55296 B

__global__ void __launch_bounds__(256, 2)
flash_h(const __half* __restrict__ Qg, const __half* __restrict__ Kg,
        const __half* __restrict__ Vtg, __half* __restrict__ Og)
{
    extern __shared__ __half hsm[];
    uint32_t* wsm = (uint32_t*)hsm;
    __half* Ph = hsm + 2 * KVBUF_H;

    const uint32_t smb = smem_u32(hsm);
    const int tid = threadIdx.x;
    const int w = tid >> 5, lane = tid & 31;
    const int g = lane >> 2, tg = lane & 3;
    const int qt = blockIdx.x;
    const int b = blockIdx.y / HH, h = blockIdx.y % HH;
    const int wm = w * 16;
    const int qlo = qt * 128 + wm;

    const __half* Qb  = Qg  + (long)b * SS * EE + h * DD;
    const __half* Kb  = Kg  + (long)b * SS * EE + h * DD;
    const __half* Vtb = Vtg + (long)(b * HH + h) * DD * SS;
    __half*       Ob  = Og  + (long)b * SS * EE + h * DD;

    // ---- stage Q tile (128 x 64 halves) into stage-0 area, extract frags ----
    {
        const int r = tid >> 1, c = (tid & 1) * 32;
        const __half* src = Qb + (long)(qt * 128 + r) * EE + c;
        const uint32_t dst = smb + (r * FH + c) * 2;
#pragma unroll
        for (int j = 0; j < 4; j++) cp_async16(dst + j * 16, src + j * 8);
        CP_COMMIT(); CP_WAIT(0);
    }
    __syncthreads();

    uint32_t qf[4][4];
#pragma unroll
    for (int ks = 0; ks < 4; ks++) {
        const int ib = (wm + g) * FW + ks * 8 + tg;
        qf[ks][0] = wsm[ib];
        qf[ks][1] = wsm[ib + 8 * FW];
        qf[ks][2] = wsm[ib + 4];
        qf[ks][3] = wsm[ib + 8 * FW + 4];
    }
    __syncthreads();

    float of[8][4];
#pragma unroll
    for (int i = 0; i < 8; i++)
#pragma unroll
        for (int j = 0; j < 4; j++) of[i][j] = 0.f;
    float m0 = NEG_BIG, m1 = NEG_BIG, l0 = 0.f, l1 = 0.f;

    const int lr = tid >> 2, lc = (tid & 3) * 16;
    const int ntiles = 2 * qt + 2;

    // prologue: tile 0 -> stage 0   (K rows: kv; Vt rows: d)
    {
        const uint32_t kdst = smb + (lr * FH + lc) * 2;
        const uint32_t vdst = smb + (KVH + lr * FH + lc) * 2;
        const __half* ksrc = Kb + (long)lr * EE + lc;
        const __half* vsrc = Vtb + (long)lr * SS + lc;
#pragma unroll
        for (int j = 0; j < 2; j++) cp_async16(kdst + j * 16, ksrc + j * 8);
#pragma unroll
        for (int j = 0; j < 2; j++) cp_async16(vdst + j * 16, vsrc + j * 8);
        CP_COMMIT();
    }

    for (int kt = 0; kt < ntiles; kt++) {
        const int cur = kt & 1, nxt = cur ^ 1;

        if (kt + 1 < ntiles) {
            const uint32_t kdst = smb + (nxt * KVBUF_H + lr * FH + lc) * 2;
            const uint32_t vdst = smb + (nxt * KVBUF_H + KVH + lr * FH + lc) * 2;
            const __half* ksrc = Kb + (long)((kt + 1) * 64 + lr) * EE + lc;
            const __half* vsrc = Vtb + (long)lr * SS + (kt + 1) * 64 + lc;
#pragma unroll
            for (int j = 0; j < 2; j++) cp_async16(kdst + j * 16, ksrc + j * 8);
#pragma unroll
            for (int j = 0; j < 2; j++) cp_async16(vdst + j * 16, vsrc + j * 8);
            CP_COMMIT();
            CP_WAIT(1);
        } else {
            CP_WAIT(0);
        }
        __syncthreads();

        const uint32_t* Kw = wsm + cur * KVBUF_H / 2;
        const uint32_t* Vw = Kw + KVH / 2;
        uint32_t* Pww = (uint32_t*)(Ph + w * 16 * FH);
        __half*   Pwh = Ph + w * 16 * FH;

        if (kt * 64 <= qlo + 15) {
            // ---- S = Q K^T (fp16 k16) ----
            float s[8][4];
#pragma unroll
            for (int nt = 0; nt < 8; nt++) {
                float c4[4] = {0.f, 0.f, 0.f, 0.f};
#pragma unroll
                for (int ks = 0; ks < 4; ks++) {
                    const int ib = (nt * 8 + g) * FW + ks * 8 + tg;
                    uint32_t bb[2] = {Kw[ib], Kw[ib + 4]};
                    mma_f16(c4, qf[ks], bb);
                }
                s[nt][0] = c4[0]; s[nt][1] = c4[1]; s[nt][2] = c4[2]; s[nt][3] = c4[3];
            }

            // ---- causal mask ----
            if (kt * 64 + 63 > qlo) {
                const int r0g = qlo + g, r1g = qlo + g + 8;
#pragma unroll
                for (int nt = 0; nt < 8; nt++) {
                    const int col = kt * 64 + nt * 8 + 2 * tg;
                    if (col     > r0g) s[nt][0] = NEG_BIG;
                    if (col + 1 > r0g) s[nt][1] = NEG_BIG;
                    if (col     > r1g) s[nt][2] = NEG_BIG;
                    if (col + 1 > r1g) s[nt][3] = NEG_BIG;
                }
            }

            // ---- online softmax ----
            float a0 = NEG_BIG, a1 = NEG_BIG;
#pragma unroll
            for (int nt = 0; nt < 8; nt++) {
                a0 = fmaxf(a0, fmaxf(s[nt][0], s[nt][1]));
                a1 = fmaxf(a1, fmaxf(s[nt][2], s[nt][3]));
            }
            a0 = fmaxf(a0, __shfl_xor_sync(0xffffffffu, a0, 1));
            a0 = fmaxf(a0, __shfl_xor_sync(0xffffffffu, a0, 2));
            a1 = fmaxf(a1, __shfl_xor_sync(0xffffffffu, a1, 1));
            a1 = fmaxf(a1, __shfl_xor_sync(0xffffffffu, a1, 2));

            const float mn0 = fmaxf(m0, a0), mn1 = fmaxf(m1, a1);
            const float cf0 = __expf(m0 - mn0), cf1 = __expf(m1 - mn1);
            m0 = mn0; m1 = mn1;

            float sum0 = 0.f, sum1 = 0.f;
#pragma unroll
            for (int nt = 0; nt < 8; nt++) {
                float p0 = __expf(s[nt][0] - m0);
                float p1 = __expf(s[nt][1] - m0);
                float p2 = __expf(s[nt][2] - m1);
                float p3 = __expf(s[nt][3] - m1);
                sum0 += p0 + p1; sum1 += p2 + p3;
                *(__half2*)&Pwh[g       * FH + nt * 8 + 2 * tg] = __floats2half2_rn(p0, p1);
                *(__half2*)&Pwh[(g + 8) * FH + nt * 8 + 2 * tg] = __floats2half2_rn(p2, p3);
            }
            sum0 += __shfl_xor_sync(0xffffffffu, sum0, 1);
            sum0 += __shfl_xor_sync(0xffffffffu, sum0, 2);
            sum1 += __shfl_xor_sync(0xffffffffu, sum1, 1);
            sum1 += __shfl_xor_sync(0xffffffffu, sum1, 2);
            l0 = l0 * cf0 + sum0;
            l1 = l1 * cf1 + sum1;
#pragma unroll
            for (int nt = 0; nt < 8; nt++) {
                of[nt][0] *= cf0; of[nt][1] *= cf0;
                of[nt][2] *= cf1; of[nt][3] *= cf1;
            }
            __syncwarp();

            // ---- O += P V (fp16 k16; B from V^T rows = d) ----
#pragma unroll
            for (int ks = 0; ks < 4; ks++) {
                uint32_t af[4];
                const int ia = g * FW + ks * 8 + tg;
                af[0] = Pww[ia];
                af[1] = Pww[ia + 8 * FW];
                af[2] = Pww[ia + 4];
                af[3] = Pww[ia + 8 * FW + 4];
#pragma unroll
                for (int dn = 0; dn < 8; dn++) {
                    const int ib = (dn * 8 + g) * FW + ks * 8 + tg;
                    uint32_t bb[2] = {Vw[ib], Vw[ib + 4]};
                    mma_f16(of[dn], af, bb);
                }
            }
        }
        __syncthreads();
    }

    // ---- epilogue: normalize, store fp16 ----
    const float i0 = 1.f / l0, i1 = 1.f / l1;
    const int r0g = qt * 128 + wm + g, r1g = r0g + 8;
#pragma unroll
    for (int dn = 0; dn < 8; dn++) {
        const int col = dn * 8 + 2 * tg;
        *(__half2*)(Ob + (long)r0g * EE + col) =
            __floats2half2_rn(of[dn][0] * i0, of[dn][1] * i0);
        *(__half2*)(Ob + (long)r1g * EE + col) =
            __floats2half2_rn(of[dn][2] * i1, of[dn][3] * i1);
    }
}

// ---------------------------------------------------------------------------
extern "C" void kernel_launch(void* const* d_in, const int* in_sizes, int n_in,
                              void* d_out, int out_size)
{
    const float* x  = (const float*)d_in[0];
    const float* Wq = (const float*)d_in[1];
    const float* Wk = (const float*)d_in[2];
    const float* Wv = (const float*)d_in[3];
    const float* Wo = (const float*)d_in[4];
    const float* bo = (const float*)d_in[5];
    float* out = (float*)d_out;

    __half *qh, *kh, *vt, *ah, *xh, *wqh, *wkh, *wvh, *woh;
    cudaGetSymbolAddress((void**)&qh,  g_qh);
    cudaGetSymbolAddress((void**)&kh,  g_kh);
    cudaGetSymbolAddress((void**)&vt,  g_vt);
    cudaGetSymbolAddress((void**)&ah,  g_ah);
    cudaGetSymbolAddress((void**)&xh,  g_xh);
    cudaGetSymbolAddress((void**)&wqh, g_wqh);
    cudaGetSymbolAddress((void**)&wkh, g_wkh);
    cudaGetSymbolAddress((void**)&wvh, g_wvh);
    cudaGetSymbolAddress((void**)&woh, g_woh);

    // prep: fp32 -> fp16
    const int xn4 = BSROWS * EE / 4, wn4 = EE * EE / 4;
    prep_h<<<(xn4 + 255) / 256, 256>>>(x,  xh,  xn4);
    prep_h<<<(wn4 + 255) / 256, 256>>>(Wq, wqh, wn4);
    prep_h<<<(wn4 + 255) / 256, 256>>>(Wk, wkh, wn4);
    prep_h<<<(wn4 + 255) / 256, 256>>>(Wv, wvh, wn4);
    prep_h<<<(wn4 + 255) / 256, 256>>>(Wo, woh, wn4);

    const int gemm_smem = 4 * TILE_W * sizeof(uint32_t);   // 73728 B
    cudaFuncSetAttribute(gemm_qkv_h,
                         cudaFuncAttributeMaxDynamicSharedMemorySize, gemm_smem);
    cudaFuncSetAttribute(gemm_h,
                         cudaFuncAttributeMaxDynamicSharedMemorySize, gemm_smem);

    // fused QKV projection: Q scaled fp16, K fp16, V^T fp16
    gemm_qkv_h<<<dim3(24, BSROWS / 128), 256, gemm_smem>>>(xh, wqh, wkh, wvh, qh, kh, vt);

    const int flash_smem = FLASH_SMEMH * sizeof(__half);   // 55296 B
    cudaFuncSetAttribute(flash_h,
                         cudaFuncAttributeMaxDynamicSharedMemorySize, flash_smem);
    flash_h<<<dim3(SS / 128, BB * HH), 256, flash_smem>>>(qh, kh, vt, ah);

    // output projection (fp16 in, fp32 out + bias)
    gemm_h<<<dim3(EE / 128, BSROWS / 128), 256, gemm_smem>>>(ah, woh, bo, out);
}

// round 13
// speedup vs baseline: 2.5976x; 1.1463x over previous
#include <cuda_runtime.h>
#include <cuda_bf16.h>
#include <cuda_fp16.h>
#include <cstdint>

#define BB 4
#define SS 2048
#define EE 1024
#define HH 16
#define DD 64
#define BSROWS (BB * SS)   // 8192

// Scratch (device globals; allocation-free per harness rules).
__device__ __half g_qh[BSROWS * EE];        // Q, fp16, pre-scaled by 1/32
__device__ __half g_kh[BSROWS * EE];        // K, fp16, row-major
__device__ __half g_vt[BSROWS * EE];        // V^T, fp16, [b][h][d][s]
__device__ __half g_ah[BSROWS * EE];        // attention out (fp16, feeds Wo)
__device__ __half g_xh[BSROWS * EE];
__device__ __half g_wqh[EE * EE];
__device__ __half g_wkh[EE * EE];
__device__ __half g_wvh[EE * EE];
__device__ __half g_woh[EE * EE];

// ---------------------------------------------------------------------------
// helpers
// ---------------------------------------------------------------------------
__device__ __forceinline__ uint32_t smem_u32(const void* p) {
    uint32_t a;
    asm("{ .reg .u64 t; cvta.to.shared.u64 t, %1; cvt.u32.u64 %0, t; }" : "=r"(a) : "l"(p));
    return a;
}
__device__ __forceinline__ void cp_async16(uint32_t dst, const void* src) {
    asm volatile("cp.async.ca.shared.global [%0], [%1], 16;" :: "r"(dst), "l"(src));
}
#define CP_COMMIT() asm volatile("cp.async.commit_group;" ::: "memory")
#define CP_WAIT(n)  asm volatile("cp.async.wait_group %0;" :: "n"(n) : "memory")

__device__ __forceinline__ void mma_f16(float* c, const uint32_t* a, const uint32_t* b) {
    asm volatile(
        "mma.sync.aligned.m16n8k16.row.col.f32.f16.f16.f32 "
        "{%0,%1,%2,%3}, {%4,%5,%6,%7}, {%8,%9}, {%0,%1,%2,%3};"
        : "+f"(c[0]), "+f"(c[1]), "+f"(c[2]), "+f"(c[3])
        : "r"(a[0]), "r"(a[1]), "r"(a[2]), "r"(a[3]), "r"(b[0]), "r"(b[1]));
}
__device__ __forceinline__ void ldsm_x4(uint32_t* r, uint32_t addr) {
    asm volatile("ldmatrix.sync.aligned.m8n8.x4.shared.b16 {%0,%1,%2,%3}, [%4];"
                 : "=r"(r[0]), "=r"(r[1]), "=r"(r[2]), "=r"(r[3]) : "r"(addr));
}

// ---------------------------------------------------------------------------
// fused prep: fp32 -> fp16 for x + 4 weights in ONE launch
// ---------------------------------------------------------------------------
__global__ void prep_all(const float* __restrict__ x,  const float* __restrict__ wq,
                         const float* __restrict__ wk, const float* __restrict__ wv,
                         const float* __restrict__ wo,
                         __half* xh, __half* wqh, __half* wkh, __half* wvh, __half* woh,
                         int xn4, int wn4)
{
    int i = blockIdx.x * blockDim.x + threadIdx.x;
    if (i >= xn4 + 4 * wn4) return;
    const float* s; __half* d; int j;
    if (i < xn4) { s = x; d = xh; j = i; }
    else {
        int t = i - xn4, sel = t / wn4; j = t - sel * wn4;
        s = (sel == 0) ? wq : (sel == 1) ? wk : (sel == 2) ? wv : wo;
        d = (sel == 0) ? wqh : (sel == 1) ? wkh : (sel == 2) ? wvh : woh;
    }
    float4 a = ((const float4*)s)[j];
    __half2* dd = (__half2*)d + 2 * j;
    dd[0] = __floats2half2_rn(a.x, a.y);
    dd[1] = __floats2half2_rn(a.z, a.w);
}

// ---------------------------------------------------------------------------
// fp16 mma.sync GEMM with ldmatrix fragment loads.
// CTA 128x128, BK=64, 8 warps (2x4), warp tile 64x32, 2-stage cp.async.
// Epilogue modes: 0 = fp32+bias, 1 = fp16*(1/32) (Q), 2 = fp16 (K),
//                 3 = fp16 transposed [b][h][d][s] (V^T)
// ---------------------------------------------------------------------------
#define HST 72                      // halves per smem row (144 B = 9 x 16B)
#define WST 36                      // words per smem row
#define TILE_W (128 * WST)          // words per matrix per stage
#define NCH 16                      // 1024 / 64
#define ROWB (HST * 2)              // bytes per smem row

__device__ __forceinline__ void gemm_body_h(
    const __half* __restrict__ A, const __half* __restrict__ W,
    const float* __restrict__ bias, void* __restrict__ Cv,
    int brow, int bcol, uint32_t smb, int mode)
{
    const int t    = threadIdx.x;
    const int lane = t & 31;
    const int w    = t >> 5;
    const int wm   = (w & 1) * 64;
    const int wn   = (w >> 1) * 32;
    const int g    = lane >> 2;
    const int tg   = lane & 3;

    // ldmatrix per-lane address components
    const int la  = lane & 7;
    const int lb8 = ((lane >> 3) & 1) * 8;
    const int lq8 = (lane >> 4) * 8;
    const uint32_t aoff = (uint32_t)((wm + la + lb8) * HST + lq8) * 2;
    const uint32_t boff = (uint32_t)((wn + la + lq8) * HST + lb8) * 2;

    const int sr = t >> 1;
    const int sc = (t & 1) * 32;
    const __half* Ag = A + (long)(brow + sr) * EE + sc;
    const __half* Wg = W + (long)(bcol + sr) * EE + sc;
    const uint32_t sdA = smb + (sr * HST + sc) * 2;
    const uint32_t sdW = sdA + TILE_W * 4;

    float acc[4][4][4];
#pragma unroll
    for (int i = 0; i < 4; i++)
#pragma unroll
        for (int j = 0; j < 4; j++)
#pragma unroll
            for (int r = 0; r < 4; r++) acc[i][j][r] = 0.f;

#pragma unroll
    for (int j = 0; j < 4; j++) {
        cp_async16(sdA + j * 16, Ag + j * 8);
        cp_async16(sdW + j * 16, Wg + j * 8);
    }
    CP_COMMIT();

    for (int kc = 0; kc < NCH; kc++) {
        const int cur = kc & 1, nxt = cur ^ 1;

        if (kc + 1 < NCH) {
            const int k0 = (kc + 1) * 64;
            const uint32_t bofs = nxt * 2 * TILE_W * 4;
#pragma unroll
            for (int j = 0; j < 4; j++) {
                cp_async16(sdA + bofs + j * 16, Ag + k0 + j * 8);
                cp_async16(sdW + bofs + j * 16, Wg + k0 + j * 8);
            }
            CP_COMMIT();
            CP_WAIT(1);
        } else {
            CP_WAIT(0);
        }
        __syncthreads();

        const uint32_t stA = smb + cur * 2 * TILE_W * 4;
        const uint32_t stB = stA + TILE_W * 4;

#pragma unroll
        for (int ks = 0; ks < 4; ks++) {
            uint32_t af[4][4], bf[4][2];
#pragma unroll
            for (int mt = 0; mt < 4; mt++)
                ldsm_x4(af[mt], stA + aoff + mt * 16 * ROWB + ks * 32);
#pragma unroll
            for (int p = 0; p < 2; p++) {
                uint32_t t4[4];
                ldsm_x4(t4, stB + boff + p * 16 * ROWB + ks * 32);
                bf[2 * p][0] = t4[0]; bf[2 * p][1] = t4[1];
                bf[2 * p + 1][0] = t4[2]; bf[2 * p + 1][1] = t4[3];
            }
#pragma unroll
            for (int mt = 0; mt < 4; mt++)
#pragma unroll
                for (int nt = 0; nt < 4; nt++)
                    mma_f16(acc[mt][nt], af[mt], bf[nt]);
        }
        __syncthreads();
    }

    if (mode == 0) {
        float* C = (float*)Cv;
#pragma unroll
        for (int mt = 0; mt < 4; mt++)
#pragma unroll
            for (int nt = 0; nt < 4; nt++) {
                const int row = brow + wm + mt * 16 + g;
                const int col = bcol + wn + nt * 8 + 2 * tg;
                float b0 = bias ? bias[col] : 0.f;
                float b1 = bias ? bias[col + 1] : 0.f;
                *(float2*)(C + (long)row * EE + col) =
                    make_float2(acc[mt][nt][0] + b0, acc[mt][nt][1] + b1);
                *(float2*)(C + (long)(row + 8) * EE + col) =
                    make_float2(acc[mt][nt][2] + b0, acc[mt][nt][3] + b1);
            }
    } else if (mode == 3) {          // V^T: [b][h][d][s]
        __half* C = (__half*)Cv;
#pragma unroll
        for (int mt = 0; mt < 4; mt++)
#pragma unroll
            for (int nt = 0; nt < 4; nt++) {
                const int row = brow + wm + mt * 16 + g;
                const int col = bcol + wn + nt * 8 + 2 * tg;
                const int bi = row >> 11, s = row & (SS - 1);
                const int h = col >> 6, d = col & 63;
                const long base = ((long)(bi * HH + h) * DD + d) * SS + s;
                C[base]          = __float2half_rn(acc[mt][nt][0]);
                C[base + SS]     = __float2half_rn(acc[mt][nt][1]);
                C[base + 8]      = __float2half_rn(acc[mt][nt][2]);
                C[base + SS + 8] = __float2half_rn(acc[mt][nt][3]);
            }
    } else {                         // fp16 row-major (Q scaled / K)
        __half* C = (__half*)Cv;
        const float sc2 = (mode == 1) ? 0.03125f : 1.0f;
#pragma unroll
        for (int mt = 0; mt < 4; mt++)
#pragma unroll
            for (int nt = 0; nt < 4; nt++) {
                const int row = brow + wm + mt * 16 + g;
                const int col = bcol + wn + nt * 8 + 2 * tg;
                *(__half2*)(C + (long)row * EE + col) =
                    __floats2half2_rn(acc[mt][nt][0] * sc2, acc[mt][nt][1] * sc2);
                *(__half2*)(C + (long)(row + 8) * EE + col) =
                    __floats2half2_rn(acc[mt][nt][2] * sc2, acc[mt][nt][3] * sc2);
            }
    }
}

__global__ void __launch_bounds__(256)
gemm_qkv_h(const __half* __restrict__ A,
           const __half* __restrict__ Wq, const __half* __restrict__ Wk,
           const __half* __restrict__ Wv,
           __half* __restrict__ Cq, __half* __restrict__ Ck, __half* __restrict__ Cv)
{
    extern __shared__ uint32_t smw[];
    const int sel  = blockIdx.x >> 3;
    const int bcol = (blockIdx.x & 7) * 128;
    const int brow = blockIdx.y * 128;
    const __half* W = (sel == 0) ? Wq : (sel == 1) ? Wk : Wv;
    void*         C = (sel == 0) ? (void*)Cq : (sel == 1) ? (void*)Ck : (void*)Cv;
    gemm_body_h(A, W, nullptr, C, brow, bcol, smem_u32(smw), sel + 1);
}

__global__ void __launch_bounds__(256)
gemm_h(const __half* __restrict__ A, const __half* __restrict__ W,
       const float* __restrict__ bias, float* __restrict__ C)
{
    extern __shared__ uint32_t smw[];
    gemm_body_h(A, W, bias, C, blockIdx.y * 128, blockIdx.x * 128,
                smem_u32(smw), 0);
}

// ---------------------------------------------------------------------------
// fp16 tensor-core flash attention with ldmatrix. qt processed in DESCENDING
// order (heavy CTAs first -> better wave packing).
// ---------------------------------------------------------------------------
#define FH 72                                // halves per smem row
#define KVH (64 * FH)                        // halves per K (or Vt) tile
#define KVBUF_H (2 * KVH)                    // halves per stage
#define NEG_BIG (-1e30f)
#define FLASH_SMEMH (2 * KVBUF_H + 8 * 16 * FH)   // 27648 halves = 55296 B

__global__ void __launch_bounds__(256, 2)
flash_h(const __half* __restrict__ Qg, const __half* __restrict__ Kg,
        const __half* __restrict__ Vtg, __half* __restrict__ Og)
{
    extern __shared__ __half hsm[];
    uint32_t* wsm = (uint32_t*)hsm;
    __half* Ph = hsm + 2 * KVBUF_H;

    const uint32_t smb = smem_u32(hsm);
    const int tid = threadIdx.x;
    const int w = tid >> 5, lane = tid & 31;
    const int g = lane >> 2, tg = lane & 3;
    const int qt = gridDim.x - 1 - blockIdx.x;   // heavy tiles first
    const int b = blockIdx.y / HH, h = blockIdx.y % HH;
    const int wm = w * 16;
    const int qlo = qt * 128 + wm;

    const int la  = lane & 7;
    const int lb8 = ((lane >> 3) & 1) * 8;
    const int lq8 = (lane >> 4) * 8;
    const uint32_t koff = (uint32_t)((la + lq8) * FH + lb8) * 2;  // B-type (K, Vt)
    const uint32_t poff = (uint32_t)((la + lb8) * FH + lq8) * 2;  // A-type (P)

    const __half* Qb  = Qg  + (long)b * SS * EE + h * DD;
    const __half* Kb  = Kg  + (long)b * SS * EE + h * DD;
    const __half* Vtb = Vtg + (long)(b * HH + h) * DD * SS;
    __half*       Ob  = Og  + (long)b * SS * EE + h * DD;

    // ---- stage Q tile into stage-0 area, extract fragments ----
    {
        const int r = tid >> 1, c = (tid & 1) * 32;
        const __half* src = Qb + (long)(qt * 128 + r) * EE + c;
        const uint32_t dst = smb + (r * FH + c) * 2;
#pragma unroll
        for (int j = 0; j < 4; j++) cp_async16(dst + j * 16, src + j * 8);
        CP_COMMIT(); CP_WAIT(0);
    }
    __syncthreads();

    uint32_t qf[4][4];
    {
        const uint32_t qoff = (uint32_t)((wm + la + lb8) * FH + lq8) * 2;
#pragma unroll
        for (int ks = 0; ks < 4; ks++)
            ldsm_x4(qf[ks], smb + qoff + ks * 32);
    }
    __syncthreads();

    float of[8][4];
#pragma unroll
    for (int i = 0; i < 8; i++)
#pragma unroll
        for (int j = 0; j < 4; j++) of[i][j] = 0.f;
    float m0 = NEG_BIG, m1 = NEG_BIG, l0 = 0.f, l1 = 0.f;

    const int lr = tid >> 2, lc = (tid & 3) * 16;
    const int ntiles = 2 * qt + 2;
    const uint32_t pbase = smb + (2 * KVBUF_H + w * 16 * FH) * 2;
    __half* Pwh = Ph + w * 16 * FH;

    // prologue: tile 0 -> stage 0
    {
        const uint32_t kdst = smb + (lr * FH + lc) * 2;
        const uint32_t vdst = smb + (KVH + lr * FH + lc) * 2;
        const __half* ksrc = Kb + (long)lr * EE + lc;
        const __half* vsrc = Vtb + (long)lr * SS + lc;
#pragma unroll
        for (int j = 0; j < 2; j++) cp_async16(kdst + j * 16, ksrc + j * 8);
#pragma unroll
        for (int j = 0; j < 2; j++) cp_async16(vdst + j * 16, vsrc + j * 8);
        CP_COMMIT();
    }

    for (int kt = 0; kt < ntiles; kt++) {
        const int cur = kt & 1, nxt = cur ^ 1;

        if (kt + 1 < ntiles) {
            const uint32_t kdst = smb + (nxt * KVBUF_H + lr * FH + lc) * 2;
            const uint32_t vdst = smb + (nxt * KVBUF_H + KVH + lr * FH + lc) * 2;
            const __half* ksrc = Kb + (long)((kt + 1) * 64 + lr) * EE + lc;
            const __half* vsrc = Vtb + (long)lr * SS + (kt + 1) * 64 + lc;
#pragma unroll
            for (int j = 0; j < 2; j++) cp_async16(kdst + j * 16, ksrc + j * 8);
#pragma unroll
            for (int j = 0; j < 2; j++) cp_async16(vdst + j * 16, vsrc + j * 8);
            CP_COMMIT();
            CP_WAIT(1);
        } else {
            CP_WAIT(0);
        }
        __syncthreads();

        const uint32_t stK = smb + cur * KVBUF_H * 2;
        const uint32_t stV = stK + KVH * 2;

        if (kt * 64 <= qlo + 15) {
            // ---- S = Q K^T ----
            float s[8][4];
#pragma unroll
            for (int nt = 0; nt < 8; nt++)
#pragma unroll
                for (int r = 0; r < 4; r++) s[nt][r] = 0.f;
#pragma unroll
            for (int ks = 0; ks < 4; ks++) {
                uint32_t kf[8][2];
#pragma unroll
                for (int p = 0; p < 4; p++) {
                    uint32_t t4[4];
                    ldsm_x4(t4, stK + koff + p * 16 * FH * 2 + ks * 32);
                    kf[2 * p][0] = t4[0]; kf[2 * p][1] = t4[1];
                    kf[2 * p + 1][0] = t4[2]; kf[2 * p + 1][1] = t4[3];
                }
#pragma unroll
                for (int nt = 0; nt < 8; nt++)
                    mma_f16(s[nt], qf[ks], kf[nt]);
            }

            // ---- causal mask ----
            if (kt * 64 + 63 > qlo) {
                const int r0g = qlo + g, r1g = qlo + g + 8;
#pragma unroll
                for (int nt = 0; nt < 8; nt++) {
                    const int col = kt * 64 + nt * 8 + 2 * tg;
                    if (col     > r0g) s[nt][0] = NEG_BIG;
                    if (col + 1 > r0g) s[nt][1] = NEG_BIG;
                    if (col     > r1g) s[nt][2] = NEG_BIG;
                    if (col + 1 > r1g) s[nt][3] = NEG_BIG;
                }
            }

            // ---- online softmax ----
            float a0 = NEG_BIG, a1 = NEG_BIG;
#pragma unroll
            for (int nt = 0; nt < 8; nt++) {
                a0 = fmaxf(a0, fmaxf(s[nt][0], s[nt][1]));
                a1 = fmaxf(a1, fmaxf(s[nt][2], s[nt][3]));
            }
            a0 = fmaxf(a0, __shfl_xor_sync(0xffffffffu, a0, 1));
            a0 = fmaxf(a0, __shfl_xor_sync(0xffffffffu, a0, 2));
            a1 = fmaxf(a1, __shfl_xor_sync(0xffffffffu, a1, 1));
            a1 = fmaxf(a1, __shfl_xor_sync(0xffffffffu, a1, 2));

            const float mn0 = fmaxf(m0, a0), mn1 = fmaxf(m1, a1);
            const float cf0 = __expf(m0 - mn0), cf1 = __expf(m1 - mn1);
            m0 = mn0; m1 = mn1;

            float sum0 = 0.f, sum1 = 0.f;
#pragma unroll
            for (int nt = 0; nt < 8; nt++) {
                float p0 = __expf(s[nt][0] - m0);
                float p1 = __expf(s[nt][1] - m0);
                float p2 = __expf(s[nt][2] - m1);
                float p3 = __expf(s[nt][3] - m1);
                sum0 += p0 + p1; sum1 += p2 + p3;
                *(__half2*)&Pwh[g       * FH + nt * 8 + 2 * tg] = __floats2half2_rn(p0, p1);
                *(__half2*)&Pwh[(g + 8) * FH + nt * 8 + 2 * tg] = __floats2half2_rn(p2, p3);
            }
            sum0 += __shfl_xor_sync(0xffffffffu, sum0, 1);
            sum0 += __shfl_xor_sync(0xffffffffu, sum0, 2);
            sum1 += __shfl_xor_sync(0xffffffffu, sum1, 1);
            sum1 += __shfl_xor_sync(0xffffffffu, sum1, 2);
            l0 = l0 * cf0 + sum0;
            l1 = l1 * cf1 + sum1;
#pragma unroll
            for (int nt = 0; nt < 8; nt++) {
                of[nt][0] *= cf0; of[nt][1] *= cf0;
                of[nt][2] *= cf1; of[nt][3] *= cf1;
            }
            __syncwarp();

            // ---- O += P V ----
#pragma unroll
            for (int ks = 0; ks < 4; ks++) {
                uint32_t af[4];
                ldsm_x4(af, pbase + poff + ks * 32);
                uint32_t vf[8][2];
#pragma unroll
                for (int p = 0; p < 4; p++) {
                    uint32_t t4[4];
                    ldsm_x4(t4, stV + koff + p * 16 * FH * 2 + ks * 32);
                    vf[2 * p][0] = t4[0]; vf[2 * p][1] = t4[1];
                    vf[2 * p + 1][0] = t4[2]; vf[2 * p + 1][1] = t4[3];
                }
#pragma unroll
                for (int dn = 0; dn < 8; dn++)
                    mma_f16(of[dn], af, vf[dn]);
            }
        }
        __syncthreads();
    }

    // ---- epilogue: normalize, store fp16 ----
    const float i0 = 1.f / l0, i1 = 1.f / l1;
    const int r0g = qt * 128 + wm + g, r1g = r0g + 8;
#pragma unroll
    for (int dn = 0; dn < 8; dn++) {
        const int col = dn * 8 + 2 * tg;
        *(__half2*)(Ob + (long)r0g * EE + col) =
            __floats2half2_rn(of[dn][0] * i0, of[dn][1] * i0);
        *(__half2*)(Ob + (long)r1g * EE + col) =
            __floats2half2_rn(of[dn][2] * i1, of[dn][3] * i1);
    }
}

// ---------------------------------------------------------------------------
extern "C" void kernel_launch(void* const* d_in, const int* in_sizes, int n_in,
                              void* d_out, int out_size)
{
    const float* x  = (const float*)d_in[0];
    const float* Wq = (const float*)d_in[1];
    const float* Wk = (const float*)d_in[2];
    const float* Wv = (const float*)d_in[3];
    const float* Wo = (const float*)d_in[4];
    const float* bo = (const float*)d_in[5];
    float* out = (float*)d_out;

    __half *qh, *kh, *vt, *ah, *xh, *wqh, *wkh, *wvh, *woh;
    cudaGetSymbolAddress((void**)&qh,  g_qh);
    cudaGetSymbolAddress((void**)&kh,  g_kh);
    cudaGetSymbolAddress((void**)&vt,  g_vt);
    cudaGetSymbolAddress((void**)&ah,  g_ah);
    cudaGetSymbolAddress((void**)&xh,  g_xh);
    cudaGetSymbolAddress((void**)&wqh, g_wqh);
    cudaGetSymbolAddress((void**)&wkh, g_wkh);
    cudaGetSymbolAddress((void**)&wvh, g_wvh);
    cudaGetSymbolAddress((void**)&woh, g_woh);

    // fused prep
    const int xn4 = BSROWS * EE / 4, wn4 = EE * EE / 4;
    const int ptot = xn4 + 4 * wn4;
    prep_all<<<(ptot + 255) / 256, 256>>>(x, Wq, Wk, Wv, Wo,
                                          xh, wqh, wkh, wvh, woh, xn4, wn4);

    const int gemm_smem = 4 * TILE_W * sizeof(uint32_t);   // 73728 B
    cudaFuncSetAttribute(gemm_qkv_h,
                         cudaFuncAttributeMaxDynamicSharedMemorySize, gemm_smem);
    cudaFuncSetAttribute(gemm_h,
                         cudaFuncAttributeMaxDynamicSharedMemorySize, gemm_smem);

    gemm_qkv_h<<<dim3(24, BSROWS / 128), 256, gemm_smem>>>(xh, wqh, wkh, wvh, qh, kh, vt);

    const int flash_smem = FLASH_SMEMH * sizeof(__half);   // 55296 B
    cudaFuncSetAttribute(flash_h,
                         cudaFuncAttributeMaxDynamicSharedMemorySize, flash_smem);
    flash_h<<<dim3(SS / 128, BB * HH), 256, flash_smem>>>(qh, kh, vt, ah);

    gemm_h<<<dim3(EE / 128, BSROWS / 128), 256, gemm_smem>>>(ah, woh, bo, out);
}

// round 14
// speedup vs baseline: 2.6084x; 1.0041x over previous
#include <cuda_runtime.h>
#include <cuda_bf16.h>
#include <cuda_fp16.h>
#include <cstdint>

#define BB 4
#define SS 2048
#define EE 1024
#define HH 16
#define DD 64
#define BSROWS (BB * SS)   // 8192

// Scratch (device globals; allocation-free per harness rules).
__device__ __half g_qh[BSROWS * EE];        // Q, fp16, pre-scaled by 1/32
__device__ __half g_kh[BSROWS * EE];        // K, fp16, row-major
__device__ __half g_vt[BSROWS * EE];        // V^T, fp16, [b][h][d][s]
__device__ __half g_ah[BSROWS * EE];        // attention out (fp16, feeds Wo)
__device__ __half g_xh[BSROWS * EE];
__device__ __half g_wqh[EE * EE];
__device__ __half g_wkh[EE * EE];
__device__ __half g_wvh[EE * EE];
__device__ __half g_woh[EE * EE];

// ---------------------------------------------------------------------------
// helpers
// ---------------------------------------------------------------------------
__device__ __forceinline__ uint32_t smem_u32(const void* p) {
    uint32_t a;
    asm("{ .reg .u64 t; cvta.to.shared.u64 t, %1; cvt.u32.u64 %0, t; }" : "=r"(a) : "l"(p));
    return a;
}
__device__ __forceinline__ void cp_async16(uint32_t dst, const void* src) {
    asm volatile("cp.async.ca.shared.global [%0], [%1], 16;" :: "r"(dst), "l"(src));
}
#define CP_COMMIT() asm volatile("cp.async.commit_group;" ::: "memory")
#define CP_WAIT(n)  asm volatile("cp.async.wait_group %0;" :: "n"(n) : "memory")

__device__ __forceinline__ void mma_f16(float* c, const uint32_t* a, const uint32_t* b) {
    asm volatile(
        "mma.sync.aligned.m16n8k16.row.col.f32.f16.f16.f32 "
        "{%0,%1,%2,%3}, {%4,%5,%6,%7}, {%8,%9}, {%0,%1,%2,%3};"
        : "+f"(c[0]), "+f"(c[1]), "+f"(c[2]), "+f"(c[3])
        : "r"(a[0]), "r"(a[1]), "r"(a[2]), "r"(a[3]), "r"(b[0]), "r"(b[1]));
}
__device__ __forceinline__ void ldsm_x4(uint32_t* r, uint32_t addr) {
    asm volatile("ldmatrix.sync.aligned.m8n8.x4.shared.b16 {%0,%1,%2,%3}, [%4];"
                 : "=r"(r[0]), "=r"(r[1]), "=r"(r[2]), "=r"(r[3]) : "r"(addr));
}

// ---------------------------------------------------------------------------
// fused prep: fp32 -> fp16 for x + 4 weights in ONE launch
// ---------------------------------------------------------------------------
__global__ void prep_all(const float* __restrict__ x,  const float* __restrict__ wq,
                         const float* __restrict__ wk, const float* __restrict__ wv,
                         const float* __restrict__ wo,
                         __half* xh, __half* wqh, __half* wkh, __half* wvh, __half* woh,
                         int xn4, int wn4)
{
    int i = blockIdx.x * blockDim.x + threadIdx.x;
    if (i >= xn4 + 4 * wn4) return;
    const float* s; __half* d; int j;
    if (i < xn4) { s = x; d = xh; j = i; }
    else {
        int t = i - xn4, sel = t / wn4; j = t - sel * wn4;
        s = (sel == 0) ? wq : (sel == 1) ? wk : (sel == 2) ? wv : wo;
        d = (sel == 0) ? wqh : (sel == 1) ? wkh : (sel == 2) ? wvh : woh;
    }
    float4 a = ((const float4*)s)[j];
    __half2* dd = (__half2*)d + 2 * j;
    dd[0] = __floats2half2_rn(a.x, a.y);
    dd[1] = __floats2half2_rn(a.z, a.w);
}

// ---------------------------------------------------------------------------
// fp16 mma.sync GEMM, CTA 128x256, 8 warps (2M x 4N), warp tile 64x64,
// BK=64, 2-stage cp.async, ldmatrix fragments.
// Epilogue modes: 0 = fp32+bias, 1 = fp16*(1/32) (Q), 2 = fp16 (K),
//                 3 = fp16 transposed [b][h][d][s] (V^T)
// ---------------------------------------------------------------------------
#define HST 72                       // halves per smem row (144 B)
#define ROWB (HST * 2)               // bytes per smem row
#define GA_H (128 * HST)             // A halves per stage (9216)
#define GB_H (256 * HST)             // B halves per stage (18432)
#define GSTG_B ((GA_H + GB_H) * 2)   // bytes per stage (55296)
#define GEMM_SMEM (2 * GSTG_B)       // 110592 B
#define NCH 16                       // 1024 / 64

__device__ __forceinline__ void gemm_body_h(
    const __half* __restrict__ A, const __half* __restrict__ W,
    const float* __restrict__ bias, void* __restrict__ Cv,
    int brow, int bcol, uint32_t smb, int mode)
{
    const int t    = threadIdx.x;
    const int lane = t & 31;
    const int w    = t >> 5;
    const int wm   = (w & 1) * 64;       // 2 warps in M
    const int wn   = (w >> 1) * 64;      // 4 warps in N
    const int g    = lane >> 2;
    const int tg   = lane & 3;

    // ldmatrix per-lane address components (proven R13 mapping)
    const int la  = lane & 7;
    const int lb8 = ((lane >> 3) & 1) * 8;
    const int lq8 = (lane >> 4) * 8;
    const uint32_t aoff = (uint32_t)((wm + la + lb8) * HST + lq8) * 2;
    const uint32_t boff = (uint32_t)((wn + la + lq8) * HST + lb8) * 2;

    // staging: A row t>>1 (half-row each), B row t (full row)
    const int sr = t >> 1;
    const int sc = (t & 1) * 32;
    const __half* Ag = A + (long)(brow + sr) * EE + sc;
    const __half* Bg = W + (long)(bcol + t) * EE;
    const uint32_t sdA = smb + (sr * HST + sc) * 2;
    const uint32_t sdB = smb + GA_H * 2 + t * ROWB;

    float acc[4][8][4];
#pragma unroll
    for (int i = 0; i < 4; i++)
#pragma unroll
        for (int j = 0; j < 8; j++)
#pragma unroll
            for (int r = 0; r < 4; r++) acc[i][j][r] = 0.f;

#pragma unroll
    for (int j = 0; j < 4; j++) cp_async16(sdA + j * 16, Ag + j * 8);
#pragma unroll
    for (int j = 0; j < 8; j++) cp_async16(sdB + j * 16, Bg + j * 8);
    CP_COMMIT();

    for (int kc = 0; kc < NCH; kc++) {
        const int cur = kc & 1, nxt = cur ^ 1;

        if (kc + 1 < NCH) {
            const int k0 = (kc + 1) * 64;
            const uint32_t bofs = nxt * GSTG_B;
#pragma unroll
            for (int j = 0; j < 4; j++) cp_async16(sdA + bofs + j * 16, Ag + k0 + j * 8);
#pragma unroll
            for (int j = 0; j < 8; j++) cp_async16(sdB + bofs + j * 16, Bg + k0 + j * 8);
            CP_COMMIT();
            CP_WAIT(1);
        } else {
            CP_WAIT(0);
        }
        __syncthreads();

        const uint32_t stA = smb + cur * GSTG_B;
        const uint32_t stB = stA + GA_H * 2;

#pragma unroll
        for (int ks = 0; ks < 4; ks++) {
            uint32_t af[4][4], bf[8][2];
#pragma unroll
            for (int mt = 0; mt < 4; mt++)
                ldsm_x4(af[mt], stA + aoff + mt * 16 * ROWB + ks * 32);
#pragma unroll
            for (int p = 0; p < 4; p++) {
                uint32_t t4[4];
                ldsm_x4(t4, stB + boff + p * 16 * ROWB + ks * 32);
                bf[2 * p][0] = t4[0]; bf[2 * p][1] = t4[1];
                bf[2 * p + 1][0] = t4[2]; bf[2 * p + 1][1] = t4[3];
            }
#pragma unroll
            for (int mt = 0; mt < 4; mt++)
#pragma unroll
                for (int nt = 0; nt < 8; nt++)
                    mma_f16(acc[mt][nt], af[mt], bf[nt]);
        }
        __syncthreads();
    }

    if (mode == 0) {
        float* C = (float*)Cv;
#pragma unroll
        for (int mt = 0; mt < 4; mt++)
#pragma unroll
            for (int nt = 0; nt < 8; nt++) {
                const int row = brow + wm + mt * 16 + g;
                const int col = bcol + wn + nt * 8 + 2 * tg;
                float b0 = bias ? bias[col] : 0.f;
                float b1 = bias ? bias[col + 1] : 0.f;
                *(float2*)(C + (long)row * EE + col) =
                    make_float2(acc[mt][nt][0] + b0, acc[mt][nt][1] + b1);
                *(float2*)(C + (long)(row + 8) * EE + col) =
                    make_float2(acc[mt][nt][2] + b0, acc[mt][nt][3] + b1);
            }
    } else if (mode == 3) {          // V^T: [b][h][d][s]
        __half* C = (__half*)Cv;
#pragma unroll
        for (int mt = 0; mt < 4; mt++)
#pragma unroll
            for (int nt = 0; nt < 8; nt++) {
                const int row = brow + wm + mt * 16 + g;
                const int col = bcol + wn + nt * 8 + 2 * tg;
                const int bi = row >> 11, s = row & (SS - 1);
                const int h = col >> 6, d = col & 63;
                const long base = ((long)(bi * HH + h) * DD + d) * SS + s;
                C[base]          = __float2half_rn(acc[mt][nt][0]);
                C[base + SS]     = __float2half_rn(acc[mt][nt][1]);
                C[base + 8]      = __float2half_rn(acc[mt][nt][2]);
                C[base + SS + 8] = __float2half_rn(acc[mt][nt][3]);
            }
    } else {                         // fp16 row-major (Q scaled / K)
        __half* C = (__half*)Cv;
        const float sc2 = (mode == 1) ? 0.03125f : 1.0f;
#pragma unroll
        for (int mt = 0; mt < 4; mt++)
#pragma unroll
            for (int nt = 0; nt < 8; nt++) {
                const int row = brow + wm + mt * 16 + g;
                const int col = bcol + wn + nt * 8 + 2 * tg;
                *(__half2*)(C + (long)row * EE + col) =
                    __floats2half2_rn(acc[mt][nt][0] * sc2, acc[mt][nt][1] * sc2);
                *(__half2*)(C + (long)(row + 8) * EE + col) =
                    __floats2half2_rn(acc[mt][nt][2] * sc2, acc[mt][nt][3] * sc2);
            }
    }
}

// Fused QKV: grid (12, 64). blockIdx.x>>2 selects matrix, &3 the 256-col block.
__global__ void __launch_bounds__(256)
gemm_qkv_h(const __half* __restrict__ A,
           const __half* __restrict__ Wq, const __half* __restrict__ Wk,
           const __half* __restrict__ Wv,
           __half* __restrict__ Cq, __half* __restrict__ Ck, __half* __restrict__ Cv)
{
    extern __shared__ uint32_t smw[];
    const int sel  = blockIdx.x >> 2;
    const int bcol = (blockIdx.x & 3) * 256;
    const int brow = blockIdx.y * 128;
    const __half* W = (sel == 0) ? Wq : (sel == 1) ? Wk : Wv;
    void*         C = (sel == 0) ? (void*)Cq : (sel == 1) ? (void*)Ck : (void*)Cv;
    gemm_body_h(A, W, nullptr, C, brow, bcol, smem_u32(smw), sel + 1);
}

// Output projection (+bias, fp32 out): grid (4, 64)
__global__ void __launch_bounds__(256)
gemm_h(const __half* __restrict__ A, const __half* __restrict__ W,
       const float* __restrict__ bias, float* __restrict__ C)
{
    extern __shared__ uint32_t smw[];
    gemm_body_h(A, W, bias, C, blockIdx.y * 128, blockIdx.x * 256,
                smem_u32(smw), 0);
}

// ---------------------------------------------------------------------------
// fp16 tensor-core flash attention with ldmatrix (R13 verbatim).
// ---------------------------------------------------------------------------
#define FH 72                                // halves per smem row
#define KVH (64 * FH)                        // halves per K (or Vt) tile
#define KVBUF_H (2 * KVH)                    // halves per stage
#define NEG_BIG (-1e30f)
#define FLASH_SMEMH (2 * KVBUF_H + 8 * 16 * FH)   // 27648 halves = 55296 B

__global__ void __launch_bounds__(256, 2)
flash_h(const __half* __restrict__ Qg, const __half* __restrict__ Kg,
        const __half* __restrict__ Vtg, __half* __restrict__ Og)
{
    extern __shared__ __half hsm[];
    __half* Ph = hsm + 2 * KVBUF_H;

    const uint32_t smb = smem_u32(hsm);
    const int tid = threadIdx.x;
    const int w = tid >> 5, lane = tid & 31;
    const int g = lane >> 2, tg = lane & 3;
    const int qt = gridDim.x - 1 - blockIdx.x;   // heavy tiles first
    const int b = blockIdx.y / HH, h = blockIdx.y % HH;
    const int wm = w * 16;
    const int qlo = qt * 128 + wm;

    const int la  = lane & 7;
    const int lb8 = ((lane >> 3) & 1) * 8;
    const int lq8 = (lane >> 4) * 8;
    const uint32_t koff = (uint32_t)((la + lq8) * FH + lb8) * 2;  // B-type (K, Vt)
    const uint32_t poff = (uint32_t)((la + lb8) * FH + lq8) * 2;  // A-type (P)

    const __half* Qb  = Qg  + (long)b * SS * EE + h * DD;
    const __half* Kb  = Kg  + (long)b * SS * EE + h * DD;
    const __half* Vtb = Vtg + (long)(b * HH + h) * DD * SS;
    __half*       Ob  = Og  + (long)b * SS * EE + h * DD;

    // ---- stage Q tile into stage-0 area, extract fragments ----
    {
        const int r = tid >> 1, c = (tid & 1) * 32;
        const __half* src = Qb + (long)(qt * 128 + r) * EE + c;
        const uint32_t dst = smb + (r * FH + c) * 2;
#pragma unroll
        for (int j = 0; j < 4; j++) cp_async16(dst + j * 16, src + j * 8);
        CP_COMMIT(); CP_WAIT(0);
    }
    __syncthreads();

    uint32_t qf[4][4];
    {
        const uint32_t qoff = (uint32_t)((wm + la + lb8) * FH + lq8) * 2;
#pragma unroll
        for (int ks = 0; ks < 4; ks++)
            ldsm_x4(qf[ks], smb + qoff + ks * 32);
    }
    __syncthreads();

    float of[8][4];
#pragma unroll
    for (int i = 0; i < 8; i++)
#pragma unroll
        for (int j = 0; j < 4; j++) of[i][j] = 0.f;
    float m0 = NEG_BIG, m1 = NEG_BIG, l0 = 0.f, l1 = 0.f;

    const int lr = tid >> 2, lc = (tid & 3) * 16;
    const int ntiles = 2 * qt + 2;
    const uint32_t pbase = smb + (2 * KVBUF_H + w * 16 * FH) * 2;
    __half* Pwh = Ph + w * 16 * FH;

    // prologue: tile 0 -> stage 0
    {
        const uint32_t kdst = smb + (lr * FH + lc) * 2;
        const uint32_t vdst = smb + (KVH + lr * FH + lc) * 2;
        const __half* ksrc = Kb + (long)lr * EE + lc;
        const __half* vsrc = Vtb + (long)lr * SS + lc;
#pragma unroll
        for (int j = 0; j < 2; j++) cp_async16(kdst + j * 16, ksrc + j * 8);
#pragma unroll
        for (int j = 0; j < 2; j++) cp_async16(vdst + j * 16, vsrc + j * 8);
        CP_COMMIT();
    }

    for (int kt = 0; kt < ntiles; kt++) {
        const int cur = kt & 1, nxt = cur ^ 1;

        if (kt + 1 < ntiles) {
            const uint32_t kdst = smb + (nxt * KVBUF_H + lr * FH + lc) * 2;
            const uint32_t vdst = smb + (nxt * KVBUF_H + KVH + lr * FH + lc) * 2;
            const __half* ksrc = Kb + (long)((kt + 1) * 64 + lr) * EE + lc;
            const __half* vsrc = Vtb + (long)lr * SS + (kt + 1) * 64 + lc;
#pragma unroll
            for (int j = 0; j < 2; j++) cp_async16(kdst + j * 16, ksrc + j * 8);
#pragma unroll
            for (int j = 0; j < 2; j++) cp_async16(vdst + j * 16, vsrc + j * 8);
            CP_COMMIT();
            CP_WAIT(1);
        } else {
            CP_WAIT(0);
        }
        __syncthreads();

        const uint32_t stK = smb + cur * KVBUF_H * 2;
        const uint32_t stV = stK + KVH * 2;

        if (kt * 64 <= qlo + 15) {
            // ---- S = Q K^T ----
            float s[8][4];
#pragma unroll
            for (int nt = 0; nt < 8; nt++)
#pragma unroll
                for (int r = 0; r < 4; r++) s[nt][r] = 0.f;
#pragma unroll
            for (int ks = 0; ks < 4; ks++) {
                uint32_t kf[8][2];
#pragma unroll
                for (int p = 0; p < 4; p++) {
                    uint32_t t4[4];
                    ldsm_x4(t4, stK + koff + p * 16 * FH * 2 + ks * 32);
                    kf[2 * p][0] = t4[0]; kf[2 * p][1] = t4[1];
                    kf[2 * p + 1][0] = t4[2]; kf[2 * p + 1][1] = t4[3];
                }
#pragma unroll
                for (int nt = 0; nt < 8; nt++)
                    mma_f16(s[nt], qf[ks], kf[nt]);
            }

            // ---- causal mask ----
            if (kt * 64 + 63 > qlo) {
                const int r0g = qlo + g, r1g = qlo + g + 8;
#pragma unroll
                for (int nt = 0; nt < 8; nt++) {
                    const int col = kt * 64 + nt * 8 + 2 * tg;
                    if (col     > r0g) s[nt][0] = NEG_BIG;
                    if (col + 1 > r0g) s[nt][1] = NEG_BIG;
                    if (col     > r1g) s[nt][2] = NEG_BIG;
                    if (col + 1 > r1g) s[nt][3] = NEG_BIG;
                }
            }

            // ---- online softmax ----
            float a0 = NEG_BIG, a1 = NEG_BIG;
#pragma unroll
            for (int nt = 0; nt < 8; nt++) {
                a0 = fmaxf(a0, fmaxf(s[nt][0], s[nt][1]));
                a1 = fmaxf(a1, fmaxf(s[nt][2], s[nt][3]));
            }
            a0 = fmaxf(a0, __shfl_xor_sync(0xffffffffu, a0, 1));
            a0 = fmaxf(a0, __shfl_xor_sync(0xffffffffu, a0, 2));
            a1 = fmaxf(a1, __shfl_xor_sync(0xffffffffu, a1, 1));
            a1 = fmaxf(a1, __shfl_xor_sync(0xffffffffu, a1, 2));

            const float mn0 = fmaxf(m0, a0), mn1 = fmaxf(m1, a1);
            const float cf0 = __expf(m0 - mn0), cf1 = __expf(m1 - mn1);
            m0 = mn0; m1 = mn1;

            float sum0 = 0.f, sum1 = 0.f;
#pragma unroll
            for (int nt = 0; nt < 8; nt++) {
                float p0 = __expf(s[nt][0] - m0);
                float p1 = __expf(s[nt][1] - m0);
                float p2 = __expf(s[nt][2] - m1);
                float p3 = __expf(s[nt][3] - m1);
                sum0 += p0 + p1; sum1 += p2 + p3;
                *(__half2*)&Pwh[g       * FH + nt * 8 + 2 * tg] = __floats2half2_rn(p0, p1);
                *(__half2*)&Pwh[(g + 8) * FH + nt * 8 + 2 * tg] = __floats2half2_rn(p2, p3);
            }
            sum0 += __shfl_xor_sync(0xffffffffu, sum0, 1);
            sum0 += __shfl_xor_sync(0xffffffffu, sum0, 2);
            sum1 += __shfl_xor_sync(0xffffffffu, sum1, 1);
            sum1 += __shfl_xor_sync(0xffffffffu, sum1, 2);
            l0 = l0 * cf0 + sum0;
            l1 = l1 * cf1 + sum1;
#pragma unroll
            for (int nt = 0; nt < 8; nt++) {
                of[nt][0] *= cf0; of[nt][1] *= cf0;
                of[nt][2] *= cf1; of[nt][3] *= cf1;
            }
            __syncwarp();

            // ---- O += P V ----
#pragma unroll
            for (int ks = 0; ks < 4; ks++) {
                uint32_t af[4];
                ldsm_x4(af, pbase + poff + ks * 32);
                uint32_t vf[8][2];
#pragma unroll
                for (int p = 0; p < 4; p++) {
                    uint32_t t4[4];
                    ldsm_x4(t4, stV + koff + p * 16 * FH * 2 + ks * 32);
                    vf[2 * p][0] = t4[0]; vf[2 * p][1] = t4[1];
                    vf[2 * p + 1][0] = t4[2]; vf[2 * p + 1][1] = t4[3];
                }
#pragma unroll
                for (int dn = 0; dn < 8; dn++)
                    mma_f16(of[dn], af, vf[dn]);
            }
        }
        __syncthreads();
    }

    // ---- epilogue: normalize, store fp16 ----
    const float i0 = 1.f / l0, i1 = 1.f / l1;
    const int r0g = qt * 128 + wm + g, r1g = r0g + 8;
#pragma unroll
    for (int dn = 0; dn < 8; dn++) {
        const int col = dn * 8 + 2 * tg;
        *(__half2*)(Ob + (long)r0g * EE + col) =
            __floats2half2_rn(of[dn][0] * i0, of[dn][1] * i0);
        *(__half2*)(Ob + (long)r1g * EE + col) =
            __floats2half2_rn(of[dn][2] * i1, of[dn][3] * i1);
    }
}

// ---------------------------------------------------------------------------
extern "C" void kernel_launch(void* const* d_in, const int* in_sizes, int n_in,
                              void* d_out, int out_size)
{
    const float* x  = (const float*)d_in[0];
    const float* Wq = (const float*)d_in[1];
    const float* Wk = (const float*)d_in[2];
    const float* Wv = (const float*)d_in[3];
    const float* Wo = (const float*)d_in[4];
    const float* bo = (const float*)d_in[5];
    float* out = (float*)d_out;

    __half *qh, *kh, *vt, *ah, *xh, *wqh, *wkh, *wvh, *woh;
    cudaGetSymbolAddress((void**)&qh,  g_qh);
    cudaGetSymbolAddress((void**)&kh,  g_kh);
    cudaGetSymbolAddress((void**)&vt,  g_vt);
    cudaGetSymbolAddress((void**)&ah,  g_ah);
    cudaGetSymbolAddress((void**)&xh,  g_xh);
    cudaGetSymbolAddress((void**)&wqh, g_wqh);
    cudaGetSymbolAddress((void**)&wkh, g_wkh);
    cudaGetSymbolAddress((void**)&wvh, g_wvh);
    cudaGetSymbolAddress((void**)&woh, g_woh);

    // fused prep
    const int xn4 = BSROWS * EE / 4, wn4 = EE * EE / 4;
    const int ptot = xn4 + 4 * wn4;
    prep_all<<<(ptot + 255) / 256, 256>>>(x, Wq, Wk, Wv, Wo,
                                          xh, wqh, wkh, wvh, woh, xn4, wn4);

    cudaFuncSetAttribute(gemm_qkv_h,
                         cudaFuncAttributeMaxDynamicSharedMemorySize, GEMM_SMEM);
    cudaFuncSetAttribute(gemm_h,
                         cudaFuncAttributeMaxDynamicSharedMemorySize, GEMM_SMEM);

    // fused QKV: grid (12, 64) — 3 matrices x 4 col-blocks of 256
    gemm_qkv_h<<<dim3(12, BSROWS / 128), 256, GEMM_SMEM>>>(xh, wqh, wkh, wvh, qh, kh, vt);

    const int flash_smem = FLASH_SMEMH * sizeof(__half);   // 55296 B
    cudaFuncSetAttribute(flash_h,
                         cudaFuncAttributeMaxDynamicSharedMemorySize, flash_smem);
    flash_h<<<dim3(SS / 128, BB * HH), 256, flash_smem>>>(qh, kh, vt, ah);

    // output projection: grid (4, 64)
    gemm_h<<<dim3(4, BSROWS / 128), 256, GEMM_SMEM>>>(ah, woh, bo, out);
}